// round 1
// baseline (speedup 1.0000x reference)
#include <cuda_runtime.h>
#include <math.h>

// Problem dims (fixed by the dataset)
#define BATCH 4
#define SEQ   4096
#define FF    768
#define NH    12
#define DH    64
#define MROWS (BATCH*SEQ)     // 16384
#define BH    (BATCH*NH)      // 48
#define KV_SPLITS 8
#define SEQ_PER_SPLIT (SEQ/KV_SPLITS)   // 512

// Scratch (static device allocations; no runtime alloc allowed)
__device__ float g_q  [MROWS * FF];
__device__ float g_k  [MROWS * FF];
__device__ float g_v  [MROWS * FF];
__device__ float g_nrm[MROWS * FF];
__device__ float g_kvp[KV_SPLITS * BH * DH * DH];
__device__ float g_ksp[KV_SPLITS * BH * DH];
__device__ float g_kv [BH * DH * DH];
__device__ float g_ks [BH * DH];

// ---------------------------------------------------------------------------
// SGEMM: C[M,N] = A[M,K] @ B[K,N] + bias[N], optional phi = elu(x)+1 epilogue
// BM=128 BN=128 BK=16, 256 threads, 8x8 per thread, double-buffered smem.
// Requires M%128==0, N%128==0, K%16==0 (true here: 16384/768/768).
// ---------------------------------------------------------------------------
#define BM 128
#define BN 128
#define BK 16
#define TM 8
#define TN 8

template <bool PHI>
__device__ __forceinline__ float epilogue(float v) {
    if (PHI) return v > 0.0f ? v + 1.0f : expf(v);   // elu(v)+1
    return v;
}

template <bool PHI>
__global__ __launch_bounds__(256, 2)
void sgemm_bias(const float* __restrict__ A, const float* __restrict__ B,
                const float* __restrict__ bias, float* __restrict__ C,
                int M, int N, int K)
{
    __shared__ float As[2][BK][BM];
    __shared__ float Bs[2][BK][BN];

    const int tid  = threadIdx.x;
    const int brow = blockIdx.y * BM;
    const int bcol = blockIdx.x * BN;

    // A tile loads: 128x16 floats = 512 float4, 2 per thread (transposed store)
    const int a_r = tid >> 2;            // 0..63  (rows a_r and a_r+64)
    const int a_c = (tid & 3) * 4;       // k offset 0/4/8/12
    // B tile loads: 16x128 floats = 512 float4, 2 per thread
    const int b_r = tid >> 5;            // 0..7  (rows b_r and b_r+8)
    const int b_c = (tid & 31) * 4;

    const int ty = tid >> 4;             // 0..15
    const int tx = tid & 15;             // 0..15

    const float* Aptr = A + (long)brow * K;
    const float* Bptr = B + bcol;

    float acc[TM][TN];
    #pragma unroll
    for (int i = 0; i < TM; i++)
        #pragma unroll
        for (int j = 0; j < TN; j++) acc[i][j] = 0.0f;

    // prologue: load tile 0 into buffer 0
    {
        #pragma unroll
        for (int i = 0; i < 2; i++) {
            int r = a_r + i * 64;
            float4 av = *(const float4*)(Aptr + (long)r * K + a_c);
            As[0][a_c + 0][r] = av.x;
            As[0][a_c + 1][r] = av.y;
            As[0][a_c + 2][r] = av.z;
            As[0][a_c + 3][r] = av.w;
        }
        #pragma unroll
        for (int i = 0; i < 2; i++) {
            int r = b_r + i * 8;
            *(float4*)&Bs[0][r][b_c] = *(const float4*)(Bptr + (long)r * N + b_c);
        }
    }
    __syncthreads();

    const int nk = K / BK;
    for (int kt = 0; kt < nk; kt++) {
        const int buf = kt & 1;
        if (kt + 1 < nk) {
            const int nb = buf ^ 1;
            const int k0 = (kt + 1) * BK;
            #pragma unroll
            for (int i = 0; i < 2; i++) {
                int r = a_r + i * 64;
                float4 av = *(const float4*)(Aptr + (long)r * K + k0 + a_c);
                As[nb][a_c + 0][r] = av.x;
                As[nb][a_c + 1][r] = av.y;
                As[nb][a_c + 2][r] = av.z;
                As[nb][a_c + 3][r] = av.w;
            }
            #pragma unroll
            for (int i = 0; i < 2; i++) {
                int r = b_r + i * 8;
                *(float4*)&Bs[nb][r][b_c] =
                    *(const float4*)(Bptr + (long)(k0 + r) * N + b_c);
            }
        }
        #pragma unroll
        for (int kk = 0; kk < BK; kk++) {
            float a_frag[TM], b_frag[TN];
            #pragma unroll
            for (int i = 0; i < TM; i++) a_frag[i] = As[buf][kk][ty * TM + i];
            #pragma unroll
            for (int j = 0; j < TN; j++) b_frag[j] = Bs[buf][kk][tx * TN + j];
            #pragma unroll
            for (int i = 0; i < TM; i++)
                #pragma unroll
                for (int j = 0; j < TN; j++)
                    acc[i][j] += a_frag[i] * b_frag[j];
        }
        __syncthreads();
    }

    // epilogue
    const float* bp = bias + bcol + tx * TN;
    float bv[TN];
    #pragma unroll
    for (int j = 0; j < TN; j++) bv[j] = bp[j];

    #pragma unroll
    for (int i = 0; i < TM; i++) {
        int row = brow + ty * TM + i;
        float* Cp = C + (long)row * N + bcol + tx * TN;
        float4 o0, o1;
        o0.x = epilogue<PHI>(acc[i][0] + bv[0]);
        o0.y = epilogue<PHI>(acc[i][1] + bv[1]);
        o0.z = epilogue<PHI>(acc[i][2] + bv[2]);
        o0.w = epilogue<PHI>(acc[i][3] + bv[3]);
        o1.x = epilogue<PHI>(acc[i][4] + bv[4]);
        o1.y = epilogue<PHI>(acc[i][5] + bv[5]);
        o1.z = epilogue<PHI>(acc[i][6] + bv[6]);
        o1.w = epilogue<PHI>(acc[i][7] + bv[7]);
        *(float4*)(Cp + 0) = o0;
        *(float4*)(Cp + 4) = o1;
    }
}

// ---------------------------------------------------------------------------
// kv partial: per (h, b, split) compute 64x64 K^T V over 512 sequence rows,
// plus partial ksum (column sums of K). 256 threads, 4x4 accum per thread.
// ---------------------------------------------------------------------------
__global__ __launch_bounds__(256)
void kv_partial_kernel()
{
    const int h = blockIdx.x;
    const int b = blockIdx.y;
    const int s = blockIdx.z;
    const int tid = threadIdx.x;

    __shared__ float ks[32][DH];
    __shared__ float vs[32][DH];

    const int tx = tid & 15;   // e-group (4 cols)
    const int ty = tid >> 4;   // d-group (4 rows)

    float acc[4][4];
    #pragma unroll
    for (int i = 0; i < 4; i++)
        #pragma unroll
        for (int j = 0; j < 4; j++) acc[i][j] = 0.0f;
    float ksum_part = 0.0f;

    const long base = ((long)b * SEQ + (long)s * SEQ_PER_SPLIT) * FF + h * DH;

    const int lrow = tid >> 4;        // 0..15 (rows lrow, lrow+16)
    const int lcol = (tid & 15) * 4;

    const int nchunks = SEQ_PER_SPLIT / 32;   // 16
    for (int c = 0; c < nchunks; c++) {
        const long cb = base + (long)c * 32 * FF;
        #pragma unroll
        for (int i = 0; i < 2; i++) {
            int r = lrow + i * 16;
            *(float4*)&ks[r][lcol] = *(const float4*)(g_k + cb + (long)r * FF + lcol);
            *(float4*)&vs[r][lcol] = *(const float4*)(g_v + cb + (long)r * FF + lcol);
        }
        __syncthreads();
        #pragma unroll 4
        for (int n = 0; n < 32; n++) {
            float a[4], bb[4];
            #pragma unroll
            for (int i = 0; i < 4; i++) a[i]  = ks[n][ty * 4 + i];
            #pragma unroll
            for (int j = 0; j < 4; j++) bb[j] = vs[n][tx * 4 + j];
            #pragma unroll
            for (int i = 0; i < 4; i++)
                #pragma unroll
                for (int j = 0; j < 4; j++)
                    acc[i][j] += a[i] * bb[j];
        }
        if (tid < DH) {
            float sum = 0.0f;
            #pragma unroll
            for (int n = 0; n < 32; n++) sum += ks[n][tid];
            ksum_part += sum;
        }
        __syncthreads();
    }

    const int hb = b * NH + h;
    float* kvout = g_kvp + ((long)s * BH + hb) * DH * DH;
    #pragma unroll
    for (int i = 0; i < 4; i++)
        #pragma unroll
        for (int j = 0; j < 4; j++)
            kvout[(ty * 4 + i) * DH + tx * 4 + j] = acc[i][j];
    if (tid < DH)
        g_ksp[((long)s * BH + hb) * DH + tid] = ksum_part;
}

// ---------------------------------------------------------------------------
// Reduce split partials
// ---------------------------------------------------------------------------
__global__ __launch_bounds__(256)
void kv_reduce_kernel()
{
    const int idx = blockIdx.x * 256 + threadIdx.x;
    if (idx < BH * DH * DH) {
        float s = 0.0f;
        #pragma unroll
        for (int p = 0; p < KV_SPLITS; p++) s += g_kvp[p * (BH * DH * DH) + idx];
        g_kv[idx] = s;
    }
    if (idx < BH * DH) {
        float s = 0.0f;
        #pragma unroll
        for (int p = 0; p < KV_SPLITS; p++) s += g_ksp[p * (BH * DH) + idx];
        g_ks[idx] = s;
    }
}

// ---------------------------------------------------------------------------
// attention out: normed[n, h*64+e] = (q[n,:] @ kv) * 1/(q[n,:] . ksum)
// grid (128 n-chunks of 32, H, B), 256 threads: thread = (row r in 0..31, eg in 0..7)
// ---------------------------------------------------------------------------
__global__ __launch_bounds__(256)
void attn_out_kernel()
{
    const int c = blockIdx.x;   // n-chunk (32 rows)
    const int h = blockIdx.y;
    const int b = blockIdx.z;
    const int tid = threadIdx.x;
    const int hb = b * NH + h;

    __shared__ float kvs[DH * DH];   // 16KB, row-major [d][e]
    __shared__ float kss[DH];
    __shared__ float qs[32][DH];
    __shared__ float zs[32];

    // load kv tile (1024 float4, 4 per thread)
    {
        const float4* kv4 = (const float4*)(g_kv + (long)hb * DH * DH);
        float4* s4 = (float4*)kvs;
        #pragma unroll
        for (int i = 0; i < 4; i++) s4[tid + i * 256] = kv4[tid + i * 256];
        if (tid < DH) kss[tid] = g_ks[(long)hb * DH + tid];
    }
    // load 32 q rows
    const long qbase = ((long)b * SEQ + (long)c * 32) * FF + h * DH;
    {
        const int lrow = tid >> 4, lcol = (tid & 15) * 4;
        #pragma unroll
        for (int i = 0; i < 2; i++) {
            int r = lrow + i * 16;
            *(float4*)&qs[r][lcol] = *(const float4*)(g_q + qbase + (long)r * FF + lcol);
        }
    }
    __syncthreads();

    const int r  = tid >> 3;   // 0..31
    const int eg = tid & 7;    // 8 output cols each

    if (eg == 0) {
        float s = 0.0f;
        #pragma unroll
        for (int dd = 0; dd < DH; dd++) s += qs[r][dd] * kss[dd];
        zs[r] = 1.0f / s;
    }
    __syncthreads();

    float4 oa = make_float4(0, 0, 0, 0), ob = make_float4(0, 0, 0, 0);
    const float4* kvrow = ((const float4*)kvs) + eg * 2;   // offset (eg*8)/4
    #pragma unroll
    for (int dd = 0; dd < DH; dd++) {
        float qv = qs[r][dd];
        float4 ka = kvrow[dd * 16];
        float4 kb = kvrow[dd * 16 + 1];
        oa.x += qv * ka.x; oa.y += qv * ka.y; oa.z += qv * ka.z; oa.w += qv * ka.w;
        ob.x += qv * kb.x; ob.y += qv * kb.y; ob.z += qv * kb.z; ob.w += qv * kb.w;
    }
    const float z = zs[r];
    oa.x *= z; oa.y *= z; oa.z *= z; oa.w *= z;
    ob.x *= z; ob.y *= z; ob.z *= z; ob.w *= z;

    float* op = g_nrm + ((long)b * SEQ + (long)c * 32 + r) * FF + h * DH + eg * 8;
    *(float4*)(op + 0) = oa;
    *(float4*)(op + 4) = ob;
}

// ---------------------------------------------------------------------------
// launch
// ---------------------------------------------------------------------------
extern "C" void kernel_launch(void* const* d_in, const int* in_sizes, int n_in,
                              void* d_out, int out_size)
{
    const float* x  = (const float*)d_in[0];
    const float* Wq = (const float*)d_in[1];
    const float* bq = (const float*)d_in[2];
    const float* Wk = (const float*)d_in[3];
    const float* bk = (const float*)d_in[4];
    const float* Wv = (const float*)d_in[5];
    const float* bv = (const float*)d_in[6];
    const float* Wo = (const float*)d_in[7];
    const float* bo = (const float*)d_in[8];
    float* out = (float*)d_out;

    float *pq, *pk, *pv, *pn;
    cudaGetSymbolAddress((void**)&pq, g_q);
    cudaGetSymbolAddress((void**)&pk, g_k);
    cudaGetSymbolAddress((void**)&pv, g_v);
    cudaGetSymbolAddress((void**)&pn, g_nrm);

    dim3 gemm_grid(FF / BN, MROWS / BM);   // (6, 128)

    // projections
    sgemm_bias<true ><<<gemm_grid, 256>>>(x, Wq, bq, pq, MROWS, FF, FF);
    sgemm_bias<true ><<<gemm_grid, 256>>>(x, Wk, bk, pk, MROWS, FF, FF);
    sgemm_bias<false><<<gemm_grid, 256>>>(x, Wv, bv, pv, MROWS, FF, FF);

    // kv summary (split-K) + reduce
    kv_partial_kernel<<<dim3(NH, BATCH, KV_SPLITS), 256>>>();
    kv_reduce_kernel<<<(BH * DH * DH + 255) / 256, 256>>>();

    // q @ kv with 1/(q.ksum) normalization
    attn_out_kernel<<<dim3(SEQ / 32, NH, BATCH), 256>>>();

    // output projection
    sgemm_bias<false><<<gemm_grid, 256>>>(pn, Wo, bo, out, MROWS, FF, FF);
}

// round 3
// speedup vs baseline: 1.7621x; 1.7621x over previous
#include <cuda_runtime.h>
#include <cuda_bf16.h>
#include <math.h>
#include <cstdint>

// ---------------------------------------------------------------------------
// Problem dims (fixed by the dataset)
// ---------------------------------------------------------------------------
#define BATCH 4
#define SEQ   4096
#define FF    768
#define NH    12
#define DH    64
#define MROWS (BATCH*SEQ)     // 16384
#define BH    (BATCH*NH)      // 48
#define KV_SPLITS 32
#define SEQ_PER_SPLIT (SEQ/KV_SPLITS)   // 128

// ---------------------------------------------------------------------------
// Static device scratch (no runtime allocation allowed)
// ---------------------------------------------------------------------------
__device__ __nv_bfloat16 g_xh[MROWS * FF];
__device__ __nv_bfloat16 g_xl[MROWS * FF];
__device__ float         g_q [MROWS * FF];
__device__ float         g_k [MROWS * FF];
__device__ float         g_v [MROWS * FF];
__device__ __nv_bfloat16 g_nh[MROWS * FF];
__device__ __nv_bfloat16 g_nl[MROWS * FF];
__device__ __nv_bfloat16 g_wh[4][FF * FF];   // transposed weights, hi part  [n][k]
__device__ __nv_bfloat16 g_wl[4][FF * FF];   // transposed weights, lo part
__device__ float g_kvp[KV_SPLITS * BH * DH * DH];
__device__ float g_ksp[KV_SPLITS * BH * DH];
__device__ float g_kv [BH * DH * DH];
__device__ float g_ks [BH * DH];

// ---------------------------------------------------------------------------
// PTX helpers (baseline sm_80-class instructions only; no tcgen05)
// ---------------------------------------------------------------------------
__device__ __forceinline__ uint32_t smem_u32(const void* p) {
    uint32_t a;
    asm("{ .reg .u64 t; cvta.to.shared.u64 t, %1; cvt.u32.u64 %0, t; }"
        : "=r"(a) : "l"(p));
    return a;
}

__device__ __forceinline__ void cp16(uint32_t dst, const void* src) {
    asm volatile("cp.async.cg.shared.global [%0], [%1], 16;" :: "r"(dst), "l"(src));
}
#define CP_COMMIT() asm volatile("cp.async.commit_group;" ::: "memory")
template <int N>
__device__ __forceinline__ void cp_wait() {
    asm volatile("cp.async.wait_group %0;" :: "n"(N) : "memory");
}

__device__ __forceinline__ void ldsm_x4(uint32_t* r, uint32_t addr) {
    asm volatile("ldmatrix.sync.aligned.m8n8.x4.shared.b16 {%0,%1,%2,%3}, [%4];"
                 : "=r"(r[0]), "=r"(r[1]), "=r"(r[2]), "=r"(r[3]) : "r"(addr));
}

// D += A * B   (m16n8k16, bf16 in, fp32 accum)
__device__ __forceinline__ void mma16816(float* d, const uint32_t* a, const uint32_t* b) {
    asm volatile(
        "mma.sync.aligned.m16n8k16.row.col.f32.bf16.bf16.f32 "
        "{%0,%1,%2,%3}, {%4,%5,%6,%7}, {%8,%9}, {%0,%1,%2,%3};"
        : "+f"(d[0]), "+f"(d[1]), "+f"(d[2]), "+f"(d[3])
        : "r"(a[0]), "r"(a[1]), "r"(a[2]), "r"(a[3]), "r"(b[0]), "r"(b[1]));
}

// ---------------------------------------------------------------------------
// mma_gemm: C[16384,768] = (Ah+Al)[M,K] @ (Bh+Bl)[N,K]^T + bias, 3-term split
// CTA tile 128x128, BK=32, 8 warps (2 M x 4 N), warp tile 64x32.
// smem rows padded to 40 bf16 (80B) -> conflict-free ldmatrix.
// ---------------------------------------------------------------------------
#define GBM 128
#define GBN 128
#define GBK 32
#define SROW 80                      // smem row stride in bytes
#define MAT_BYTES (128 * SROW)       // 10240
#define AH_OFF 0
#define AL_OFF (1 * MAT_BYTES)
#define BHOFF  (2 * MAT_BYTES)
#define BLOFF  (3 * MAT_BYTES)
#define STAGE_BYTES (4 * MAT_BYTES)  // 40960
#define SMEM_DYN (2 * STAGE_BYTES)   // 81920

template <bool PHI>
__device__ __forceinline__ float ep(float v) {
    if (PHI) return v > 0.0f ? v + 1.0f : expf(v);   // elu(v)+1
    return v;
}

__device__ __forceinline__ void load_stage(uint32_t st,
        const __nv_bfloat16* __restrict__ Ah, const __nv_bfloat16* __restrict__ Al,
        const __nv_bfloat16* __restrict__ Bh, const __nv_bfloat16* __restrict__ Bl,
        int brow, int bcol, int kbase, int tid)
{
    #pragma unroll
    for (int i = 0; i < 2; i++) {
        int c  = tid + i * 256;      // 0..511
        int r  = c >> 2;             // 0..127
        int kc = c & 3;              // 16B chunk within 64B row
        uint32_t d = st + (uint32_t)r * SROW + (uint32_t)kc * 16;
        size_t goA = (size_t)(brow + r) * FF + kbase + kc * 8;
        size_t goB = (size_t)(bcol + r) * FF + kbase + kc * 8;
        cp16(d + AH_OFF, Ah + goA);
        cp16(d + AL_OFF, Al + goA);
        cp16(d + BHOFF,  Bh + goB);
        cp16(d + BLOFF,  Bl + goB);
    }
}

template <bool PHI>
__global__ __launch_bounds__(256, 1)
void mma_gemm(const __nv_bfloat16* __restrict__ Ah, const __nv_bfloat16* __restrict__ Al,
              const __nv_bfloat16* __restrict__ Bh, const __nv_bfloat16* __restrict__ Bl,
              const float* __restrict__ bias, float* __restrict__ C)
{
    extern __shared__ char dsm[];
    const uint32_t sb = smem_u32(dsm);

    const int tid  = threadIdx.x;
    const int warp = tid >> 5;
    const int lane = tid & 31;
    const int wm   = warp & 1;        // 0..1 -> M offset 64*wm
    const int wn   = warp >> 1;       // 0..3 -> N offset 32*wn
    const int brow = blockIdx.y * GBM;
    const int bcol = blockIdx.x * GBN;

    float acc[4][4][4];
    #pragma unroll
    for (int i = 0; i < 4; i++)
        #pragma unroll
        for (int j = 0; j < 4; j++)
            #pragma unroll
            for (int q = 0; q < 4; q++) acc[i][j][q] = 0.0f;

    load_stage(sb, Ah, Al, Bh, Bl, brow, bcol, 0, tid);
    CP_COMMIT();

    const int NIT = FF / GBK;   // 24
    for (int it = 0; it < NIT; it++) {
        const uint32_t st = sb + (uint32_t)(it & 1) * STAGE_BYTES;
        if (it + 1 < NIT) {
            load_stage(sb + (uint32_t)((it + 1) & 1) * STAGE_BYTES,
                       Ah, Al, Bh, Bl, brow, bcol, (it + 1) * GBK, tid);
            CP_COMMIT();
            cp_wait<1>();
        } else {
            cp_wait<0>();
        }
        __syncthreads();

        #pragma unroll
        for (int ks = 0; ks < 2; ks++) {
            uint32_t Ahf[4][4], Alf[4][4], Bhf[4][2], Blf[4][2];
            const uint32_t koff = (uint32_t)(ks * 16 + (lane >> 4) * 8) * 2;
            #pragma unroll
            for (int mf = 0; mf < 4; mf++) {
                uint32_t ad = st + (uint32_t)(wm * 64 + mf * 16 + (lane & 15)) * SROW + koff;
                ldsm_x4(Ahf[mf], ad + AH_OFF);
                ldsm_x4(Alf[mf], ad + AL_OFF);
            }
            #pragma unroll
            for (int bq = 0; bq < 2; bq++) {
                uint32_t bd = st + (uint32_t)(wn * 32 + bq * 16 + (lane & 15)) * SROW + koff;
                uint32_t t[4];
                ldsm_x4(t, bd + BHOFF);
                Bhf[bq * 2][0] = t[0]; Bhf[bq * 2][1] = t[2];
                Bhf[bq * 2 + 1][0] = t[1]; Bhf[bq * 2 + 1][1] = t[3];
                ldsm_x4(t, bd + BLOFF);
                Blf[bq * 2][0] = t[0]; Blf[bq * 2][1] = t[2];
                Blf[bq * 2 + 1][0] = t[1]; Blf[bq * 2 + 1][1] = t[3];
            }
            #pragma unroll
            for (int mf = 0; mf < 4; mf++)
                #pragma unroll
                for (int nf = 0; nf < 4; nf++) {
                    mma16816(acc[mf][nf], Ahf[mf], Bhf[nf]);
                    mma16816(acc[mf][nf], Ahf[mf], Blf[nf]);
                    mma16816(acc[mf][nf], Alf[mf], Bhf[nf]);
                }
        }
        __syncthreads();
    }

    // epilogue: bias + optional phi, float2 stores
    #pragma unroll
    for (int nf = 0; nf < 4; nf++) {
        const int col = bcol + wn * 32 + nf * 8 + 2 * (lane & 3);
        const float b0 = bias[col], b1 = bias[col + 1];
        #pragma unroll
        for (int mf = 0; mf < 4; mf++) {
            const int r0 = brow + wm * 64 + mf * 16 + (lane >> 2);
            float2 v;
            v.x = ep<PHI>(acc[mf][nf][0] + b0);
            v.y = ep<PHI>(acc[mf][nf][1] + b1);
            *(float2*)(C + (size_t)r0 * FF + col) = v;
            v.x = ep<PHI>(acc[mf][nf][2] + b0);
            v.y = ep<PHI>(acc[mf][nf][3] + b1);
            *(float2*)(C + (size_t)(r0 + 8) * FF + col) = v;
        }
    }
}

// ---------------------------------------------------------------------------
// conversions
// ---------------------------------------------------------------------------
__global__ __launch_bounds__(256)
void conv_x(const float4* __restrict__ in, __nv_bfloat16* __restrict__ xh,
            __nv_bfloat16* __restrict__ xl, int n4)
{
    for (int i = blockIdx.x * 256 + threadIdx.x; i < n4; i += gridDim.x * 256) {
        float4 v = in[i];
        union { __nv_bfloat16 b[4]; uint2 u; } H, L;
        H.b[0] = __float2bfloat16(v.x);
        H.b[1] = __float2bfloat16(v.y);
        H.b[2] = __float2bfloat16(v.z);
        H.b[3] = __float2bfloat16(v.w);
        L.b[0] = __float2bfloat16(v.x - __bfloat162float(H.b[0]));
        L.b[1] = __float2bfloat16(v.y - __bfloat162float(H.b[1]));
        L.b[2] = __float2bfloat16(v.z - __bfloat162float(H.b[2]));
        L.b[3] = __float2bfloat16(v.w - __bfloat162float(H.b[3]));
        *(uint2*)(xh + 4 * (size_t)i) = H.u;
        *(uint2*)(xl + 4 * (size_t)i) = L.u;
    }
}

// transpose + split: Wt[n][k] = W[k][n]
__global__ __launch_bounds__(256)
void conv_w(const float* __restrict__ W, __nv_bfloat16* __restrict__ Th,
            __nv_bfloat16* __restrict__ Tl)
{
    __shared__ float t[32][33];
    const int bx = blockIdx.x * 32, by = blockIdx.y * 32;
    const int tx = threadIdx.x, ty = threadIdx.y;
    #pragma unroll
    for (int i = ty; i < 32; i += 8)
        t[i][tx] = W[(size_t)(by + i) * FF + bx + tx];
    __syncthreads();
    #pragma unroll
    for (int i = ty; i < 32; i += 8) {
        float v = t[tx][i];   // = W[by+tx][bx+i]
        __nv_bfloat16 h = __float2bfloat16(v);
        __nv_bfloat16 l = __float2bfloat16(v - __bfloat162float(h));
        size_t off = (size_t)(bx + i) * FF + by + tx;
        Th[off] = h;
        Tl[off] = l;
    }
}

// ---------------------------------------------------------------------------
// kv partial: per (h, b, split) compute 64x64 K^T V over SEQ_PER_SPLIT rows
// ---------------------------------------------------------------------------
__global__ __launch_bounds__(256)
void kv_partial_kernel()
{
    const int h = blockIdx.x;
    const int b = blockIdx.y;
    const int s = blockIdx.z;
    const int tid = threadIdx.x;

    __shared__ float ks[32][DH];
    __shared__ float vs[32][DH];

    const int tx = tid & 15;
    const int ty = tid >> 4;

    float acc[4][4];
    #pragma unroll
    for (int i = 0; i < 4; i++)
        #pragma unroll
        for (int j = 0; j < 4; j++) acc[i][j] = 0.0f;
    float ksum_part = 0.0f;

    const size_t base = ((size_t)b * SEQ + (size_t)s * SEQ_PER_SPLIT) * FF + h * DH;
    const int lrow = tid >> 4;
    const int lcol = (tid & 15) * 4;

    const int nchunks = SEQ_PER_SPLIT / 32;
    for (int c = 0; c < nchunks; c++) {
        const size_t cb = base + (size_t)c * 32 * FF;
        #pragma unroll
        for (int i = 0; i < 2; i++) {
            int r = lrow + i * 16;
            *(float4*)&ks[r][lcol] = *(const float4*)(g_k + cb + (size_t)r * FF + lcol);
            *(float4*)&vs[r][lcol] = *(const float4*)(g_v + cb + (size_t)r * FF + lcol);
        }
        __syncthreads();
        #pragma unroll 4
        for (int n = 0; n < 32; n++) {
            float a[4], bb[4];
            #pragma unroll
            for (int i = 0; i < 4; i++) a[i]  = ks[n][ty * 4 + i];
            #pragma unroll
            for (int j = 0; j < 4; j++) bb[j] = vs[n][tx * 4 + j];
            #pragma unroll
            for (int i = 0; i < 4; i++)
                #pragma unroll
                for (int j = 0; j < 4; j++)
                    acc[i][j] += a[i] * bb[j];
        }
        if (tid < DH) {
            float sum = 0.0f;
            #pragma unroll
            for (int n = 0; n < 32; n++) sum += ks[n][tid];
            ksum_part += sum;
        }
        __syncthreads();
    }

    const int hb = b * NH + h;
    float* kvout = g_kvp + ((size_t)s * BH + hb) * DH * DH;
    #pragma unroll
    for (int i = 0; i < 4; i++)
        #pragma unroll
        for (int j = 0; j < 4; j++)
            kvout[(ty * 4 + i) * DH + tx * 4 + j] = acc[i][j];
    if (tid < DH)
        g_ksp[((size_t)s * BH + hb) * DH + tid] = ksum_part;
}

__global__ __launch_bounds__(256)
void kv_reduce_kernel()
{
    const int idx = blockIdx.x * 256 + threadIdx.x;
    if (idx < BH * DH * DH) {
        float s = 0.0f;
        #pragma unroll
        for (int p = 0; p < KV_SPLITS; p++) s += g_kvp[(size_t)p * (BH * DH * DH) + idx];
        g_kv[idx] = s;
    }
    if (idx < BH * DH) {
        float s = 0.0f;
        #pragma unroll
        for (int p = 0; p < KV_SPLITS; p++) s += g_ksp[(size_t)p * (BH * DH) + idx];
        g_ks[idx] = s;
    }
}

// ---------------------------------------------------------------------------
// attention out: normed = (q @ kv) * 1/(q . ksum); writes hi/lo bf16
// ---------------------------------------------------------------------------
__global__ __launch_bounds__(256)
void attn_out_kernel()
{
    const int c = blockIdx.x;
    const int h = blockIdx.y;
    const int b = blockIdx.z;
    const int tid = threadIdx.x;
    const int hb = b * NH + h;

    __shared__ float kvs[DH * DH];
    __shared__ float kss[DH];
    __shared__ float qs[32][DH];
    __shared__ float zs[32];

    {
        const float4* kv4 = (const float4*)(g_kv + (size_t)hb * DH * DH);
        float4* s4 = (float4*)kvs;
        #pragma unroll
        for (int i = 0; i < 4; i++) s4[tid + i * 256] = kv4[tid + i * 256];
        if (tid < DH) kss[tid] = g_ks[(size_t)hb * DH + tid];
    }
    const size_t qbase = ((size_t)b * SEQ + (size_t)c * 32) * FF + h * DH;
    {
        const int lrow = tid >> 4, lcol = (tid & 15) * 4;
        #pragma unroll
        for (int i = 0; i < 2; i++) {
            int r = lrow + i * 16;
            *(float4*)&qs[r][lcol] = *(const float4*)(g_q + qbase + (size_t)r * FF + lcol);
        }
    }
    __syncthreads();

    const int r  = tid >> 3;
    const int eg = tid & 7;

    if (eg == 0) {
        float s = 0.0f;
        #pragma unroll
        for (int dd = 0; dd < DH; dd++) s += qs[r][dd] * kss[dd];
        zs[r] = 1.0f / s;
    }
    __syncthreads();

    float4 oa = make_float4(0, 0, 0, 0), ob = make_float4(0, 0, 0, 0);
    const float4* kvrow = ((const float4*)kvs) + eg * 2;
    #pragma unroll
    for (int dd = 0; dd < DH; dd++) {
        float qv = qs[r][dd];
        float4 ka = kvrow[dd * 16];
        float4 kb = kvrow[dd * 16 + 1];
        oa.x += qv * ka.x; oa.y += qv * ka.y; oa.z += qv * ka.z; oa.w += qv * ka.w;
        ob.x += qv * kb.x; ob.y += qv * kb.y; ob.z += qv * kb.z; ob.w += qv * kb.w;
    }
    const float z = zs[r];
    float o[8] = { oa.x * z, oa.y * z, oa.z * z, oa.w * z,
                   ob.x * z, ob.y * z, ob.z * z, ob.w * z };

    union { __nv_bfloat16 b2[8]; uint4 u; } H, L;
    #pragma unroll
    for (int j = 0; j < 8; j++) {
        H.b2[j] = __float2bfloat16(o[j]);
        L.b2[j] = __float2bfloat16(o[j] - __bfloat162float(H.b2[j]));
    }
    const size_t off = ((size_t)b * SEQ + (size_t)c * 32 + r) * FF + h * DH + eg * 8;
    *(uint4*)(g_nh + off) = H.u;
    *(uint4*)(g_nl + off) = L.u;
}

// ---------------------------------------------------------------------------
// launch
// ---------------------------------------------------------------------------
extern "C" void kernel_launch(void* const* d_in, const int* in_sizes, int n_in,
                              void* d_out, int out_size)
{
    const float* x  = (const float*)d_in[0];
    const float* Wq = (const float*)d_in[1];
    const float* bq = (const float*)d_in[2];
    const float* Wk = (const float*)d_in[3];
    const float* bk = (const float*)d_in[4];
    const float* Wv = (const float*)d_in[5];
    const float* bv = (const float*)d_in[6];
    const float* Wo = (const float*)d_in[7];
    const float* bo = (const float*)d_in[8];
    float* out = (float*)d_out;

    __nv_bfloat16 *pxh, *pxl, *pnh, *pnl, *pwh, *pwl;
    float *pq, *pk, *pv;
    cudaGetSymbolAddress((void**)&pxh, g_xh);
    cudaGetSymbolAddress((void**)&pxl, g_xl);
    cudaGetSymbolAddress((void**)&pnh, g_nh);
    cudaGetSymbolAddress((void**)&pnl, g_nl);
    cudaGetSymbolAddress((void**)&pwh, g_wh);
    cudaGetSymbolAddress((void**)&pwl, g_wl);
    cudaGetSymbolAddress((void**)&pq,  g_q);
    cudaGetSymbolAddress((void**)&pk,  g_k);
    cudaGetSymbolAddress((void**)&pv,  g_v);

    static bool attr_done = false;
    if (!attr_done) {
        cudaFuncSetAttribute(mma_gemm<true>,  cudaFuncAttributeMaxDynamicSharedMemorySize, SMEM_DYN);
        cudaFuncSetAttribute(mma_gemm<false>, cudaFuncAttributeMaxDynamicSharedMemorySize, SMEM_DYN);
        attr_done = true;
    }

    // weight transpose + split
    dim3 wgrid(FF / 32, FF / 32);
    conv_w<<<wgrid, dim3(32, 8)>>>(Wq, pwh + 0 * (size_t)FF * FF, pwl + 0 * (size_t)FF * FF);
    conv_w<<<wgrid, dim3(32, 8)>>>(Wk, pwh + 1 * (size_t)FF * FF, pwl + 1 * (size_t)FF * FF);
    conv_w<<<wgrid, dim3(32, 8)>>>(Wv, pwh + 2 * (size_t)FF * FF, pwl + 2 * (size_t)FF * FF);
    conv_w<<<wgrid, dim3(32, 8)>>>(Wo, pwh + 3 * (size_t)FF * FF, pwl + 3 * (size_t)FF * FF);

    // x split
    conv_x<<<2048, 256>>>((const float4*)x, pxh, pxl, MROWS * FF / 4);

    dim3 ggrid(FF / GBN, MROWS / GBM);   // (6, 128)
    // projections (tensor cores via mma.sync)
    mma_gemm<true ><<<ggrid, 256, SMEM_DYN>>>(pxh, pxl, pwh + 0 * (size_t)FF * FF, pwl + 0 * (size_t)FF * FF, bq, pq);
    mma_gemm<true ><<<ggrid, 256, SMEM_DYN>>>(pxh, pxl, pwh + 1 * (size_t)FF * FF, pwl + 1 * (size_t)FF * FF, bk, pk);
    mma_gemm<false><<<ggrid, 256, SMEM_DYN>>>(pxh, pxl, pwh + 2 * (size_t)FF * FF, pwl + 2 * (size_t)FF * FF, bv, pv);

    // kv summary + reduce
    kv_partial_kernel<<<dim3(NH, BATCH, KV_SPLITS), 256>>>();
    kv_reduce_kernel<<<(BH * DH * DH + 255) / 256, 256>>>();

    // attention output (writes hi/lo bf16)
    attn_out_kernel<<<dim3(SEQ / 32, NH, BATCH), 256>>>();

    // output projection
    mma_gemm<false><<<ggrid, 256, SMEM_DYN>>>(pnh, pnl, pwh + 3 * (size_t)FF * FF, pwl + 3 * (size_t)FF * FF, bo, out);
}

// round 4
// speedup vs baseline: 1.8179x; 1.0317x over previous
#include <cuda_runtime.h>
#include <cuda_bf16.h>
#include <math.h>
#include <cstdint>

// ---------------------------------------------------------------------------
// Problem dims (fixed by the dataset)
// ---------------------------------------------------------------------------
#define BATCH 4
#define SEQ   4096
#define FF    768
#define NH    12
#define DH    64
#define MROWS (BATCH*SEQ)     // 16384
#define BH    (BATCH*NH)      // 48
#define KV_SPLITS 32
#define SEQ_PER_SPLIT (SEQ/KV_SPLITS)   // 128

// ---------------------------------------------------------------------------
// Static device scratch (no runtime allocation allowed)
// ---------------------------------------------------------------------------
__device__ __nv_bfloat16 g_xh[MROWS * FF];
__device__ __nv_bfloat16 g_xl[MROWS * FF];
__device__ float         g_q [MROWS * FF];
__device__ float         g_k [MROWS * FF];
__device__ float         g_v [MROWS * FF];
__device__ __nv_bfloat16 g_nh[MROWS * FF];
__device__ __nv_bfloat16 g_nl[MROWS * FF];
__device__ __nv_bfloat16 g_wh[4][FF * FF];   // transposed weights, hi part  [n][k]
__device__ __nv_bfloat16 g_wl[4][FF * FF];   // transposed weights, lo part
__device__ float g_kvp[KV_SPLITS * BH * DH * DH];
__device__ float g_ksp[KV_SPLITS * BH * DH];
__device__ float g_kv [BH * DH * DH];
__device__ float g_ks [BH * DH];

// ---------------------------------------------------------------------------
// PTX helpers (baseline sm_80-class instructions only; no tcgen05)
// ---------------------------------------------------------------------------
__device__ __forceinline__ uint32_t smem_u32(const void* p) {
    uint32_t a;
    asm("{ .reg .u64 t; cvta.to.shared.u64 t, %1; cvt.u32.u64 %0, t; }"
        : "=r"(a) : "l"(p));
    return a;
}

__device__ __forceinline__ void cp16(uint32_t dst, const void* src) {
    asm volatile("cp.async.cg.shared.global [%0], [%1], 16;" :: "r"(dst), "l"(src));
}
#define CP_COMMIT() asm volatile("cp.async.commit_group;" ::: "memory")
template <int N>
__device__ __forceinline__ void cp_wait() {
    asm volatile("cp.async.wait_group %0;" :: "n"(N) : "memory");
}

__device__ __forceinline__ void ldsm_x4(uint32_t* r, uint32_t addr) {
    asm volatile("ldmatrix.sync.aligned.m8n8.x4.shared.b16 {%0,%1,%2,%3}, [%4];"
                 : "=r"(r[0]), "=r"(r[1]), "=r"(r[2]), "=r"(r[3]) : "r"(addr));
}

// D += A * B   (m16n8k16, bf16 in, fp32 accum)
__device__ __forceinline__ void mma16816(float* d, const uint32_t* a, const uint32_t* b) {
    asm volatile(
        "mma.sync.aligned.m16n8k16.row.col.f32.bf16.bf16.f32 "
        "{%0,%1,%2,%3}, {%4,%5,%6,%7}, {%8,%9}, {%0,%1,%2,%3};"
        : "+f"(d[0]), "+f"(d[1]), "+f"(d[2]), "+f"(d[3])
        : "r"(a[0]), "r"(a[1]), "r"(a[2]), "r"(a[3]), "r"(b[0]), "r"(b[1]));
}

// ---------------------------------------------------------------------------
// mma_gemm: C[16384,768] = (Ah+Al)[M,K] @ (Bh+Bl)[N,K]^T + bias, 3-term split
// CTA tile 128x128, BK=32, 512 threads = 16 warps (2 M x 8 N), warp 64x16.
// 4-stage cp.async pipeline, ONE __syncthreads per k-iter, prefetch depth 3.
// smem rows padded to 80B -> conflict-free ldmatrix.
// ---------------------------------------------------------------------------
#define GBM 128
#define GBN 128
#define GBK 32
#define SROW 80                      // smem row stride in bytes
#define MAT_BYTES (128 * SROW)       // 10240
#define AH_OFF 0
#define AL_OFF (1 * MAT_BYTES)
#define BHOFF  (2 * MAT_BYTES)
#define BLOFF  (3 * MAT_BYTES)
#define STAGE_BYTES (4 * MAT_BYTES)  // 40960
#define NSTAGE 4
#define SMEM_DYN (NSTAGE * STAGE_BYTES)   // 163840
#define NIT (FF / GBK)               // 24

template <bool PHI>
__device__ __forceinline__ float ep(float v) {
    if (PHI) return v > 0.0f ? v + 1.0f : expf(v);   // elu(v)+1
    return v;
}

// 512 threads: each thread loads 4 x 16B (one 16B chunk of one row per matrix pair)
__device__ __forceinline__ void load_stage(uint32_t st,
        const __nv_bfloat16* __restrict__ Ah, const __nv_bfloat16* __restrict__ Al,
        const __nv_bfloat16* __restrict__ Bh, const __nv_bfloat16* __restrict__ Bl,
        int brow, int bcol, int kbase, int tid)
{
    const int r  = tid >> 2;             // 0..127
    const int kc = tid & 3;              // 16B chunk within 64B row
    const uint32_t d = st + (uint32_t)r * SROW + (uint32_t)kc * 16;
    const size_t goA = (size_t)(brow + r) * FF + kbase + kc * 8;
    const size_t goB = (size_t)(bcol + r) * FF + kbase + kc * 8;
    cp16(d + AH_OFF, Ah + goA);
    cp16(d + AL_OFF, Al + goA);
    cp16(d + BHOFF,  Bh + goB);
    cp16(d + BLOFF,  Bl + goB);
}

template <bool PHI>
__global__ __launch_bounds__(512, 1)
void mma_gemm(const __nv_bfloat16* __restrict__ Ah, const __nv_bfloat16* __restrict__ Al,
              const __nv_bfloat16* __restrict__ Bh, const __nv_bfloat16* __restrict__ Bl,
              const float* __restrict__ bias, float* __restrict__ C)
{
    extern __shared__ char dsm[];
    const uint32_t sb = smem_u32(dsm);

    const int tid  = threadIdx.x;
    const int warp = tid >> 5;
    const int lane = tid & 31;
    const int wm   = warp & 1;        // 0..1 -> M offset 64*wm
    const int wn   = warp >> 1;       // 0..7 -> N offset 16*wn
    const int brow = blockIdx.y * GBM;
    const int bcol = blockIdx.x * GBN;

    float acc[4][2][4];
    #pragma unroll
    for (int i = 0; i < 4; i++)
        #pragma unroll
        for (int j = 0; j < 2; j++)
            #pragma unroll
            for (int q = 0; q < 4; q++) acc[i][j][q] = 0.0f;

    // prologue: prefetch stages 0,1,2
    #pragma unroll
    for (int s = 0; s < NSTAGE - 1; s++) {
        load_stage(sb + (uint32_t)s * STAGE_BYTES, Ah, Al, Bh, Bl,
                   brow, bcol, s * GBK, tid);
        CP_COMMIT();
    }

    // per-warp base addresses (row part varies per fragment; precompute lane bits)
    const uint32_t a_row  = (uint32_t)(wm * 64 + (lane & 15)) * SROW;
    const uint32_t b_row  = (uint32_t)(wn * 16 + (lane & 15)) * SROW;
    const uint32_t k_lane = (uint32_t)((lane >> 4) * 8) * 2;   // 0 or 16 bytes

    for (int it = 0; it < NIT; it++) {
        // retire the cp.async group that filled stage `it`
        if (it < NIT - 2)      cp_wait<2>();
        else if (it == NIT - 2) cp_wait<1>();
        else                    cp_wait<0>();
        __syncthreads();

        // prefetch stage it+3 into the slot freed by stage it-1
        if (it + NSTAGE - 1 < NIT) {
            load_stage(sb + (uint32_t)((it + NSTAGE - 1) & (NSTAGE - 1)) * STAGE_BYTES,
                       Ah, Al, Bh, Bl, brow, bcol, (it + NSTAGE - 1) * GBK, tid);
            CP_COMMIT();
        }

        const uint32_t st = sb + (uint32_t)(it & (NSTAGE - 1)) * STAGE_BYTES;

        #pragma unroll
        for (int ks = 0; ks < 2; ks++) {
            const uint32_t koff = (uint32_t)(ks * 32) + k_lane;   // bytes
            uint32_t Ahf[4][4], Alf[4][4], Bhf[2][2], Blf[2][2];
            #pragma unroll
            for (int mf = 0; mf < 4; mf++) {
                const uint32_t ad = st + a_row + (uint32_t)(mf * 16) * SROW + koff;
                ldsm_x4(Ahf[mf], ad + AH_OFF);
                ldsm_x4(Alf[mf], ad + AL_OFF);
            }
            {
                const uint32_t bd = st + b_row + koff;
                uint32_t t[4];
                ldsm_x4(t, bd + BHOFF);
                Bhf[0][0] = t[0]; Bhf[0][1] = t[2];
                Bhf[1][0] = t[1]; Bhf[1][1] = t[3];
                ldsm_x4(t, bd + BLOFF);
                Blf[0][0] = t[0]; Blf[0][1] = t[2];
                Blf[1][0] = t[1]; Blf[1][1] = t[3];
            }
            #pragma unroll
            for (int mf = 0; mf < 4; mf++)
                #pragma unroll
                for (int nf = 0; nf < 2; nf++) {
                    mma16816(acc[mf][nf], Ahf[mf], Bhf[nf]);
                    mma16816(acc[mf][nf], Ahf[mf], Blf[nf]);
                    mma16816(acc[mf][nf], Alf[mf], Bhf[nf]);
                }
        }
    }

    // epilogue: bias + optional phi, float2 stores
    #pragma unroll
    for (int nf = 0; nf < 2; nf++) {
        const int col = bcol + wn * 16 + nf * 8 + 2 * (lane & 3);
        const float b0 = bias[col], b1 = bias[col + 1];
        #pragma unroll
        for (int mf = 0; mf < 4; mf++) {
            const int r0 = brow + wm * 64 + mf * 16 + (lane >> 2);
            float2 v;
            v.x = ep<PHI>(acc[mf][nf][0] + b0);
            v.y = ep<PHI>(acc[mf][nf][1] + b1);
            *(float2*)(C + (size_t)r0 * FF + col) = v;
            v.x = ep<PHI>(acc[mf][nf][2] + b0);
            v.y = ep<PHI>(acc[mf][nf][3] + b1);
            *(float2*)(C + (size_t)(r0 + 8) * FF + col) = v;
        }
    }
}

// ---------------------------------------------------------------------------
// conversions
// ---------------------------------------------------------------------------
__global__ __launch_bounds__(256)
void conv_x(const float4* __restrict__ in, __nv_bfloat16* __restrict__ xh,
            __nv_bfloat16* __restrict__ xl, int n4)
{
    for (int i = blockIdx.x * 256 + threadIdx.x; i < n4; i += gridDim.x * 256) {
        float4 v = in[i];
        union { __nv_bfloat16 b[4]; uint2 u; } H, L;
        H.b[0] = __float2bfloat16(v.x);
        H.b[1] = __float2bfloat16(v.y);
        H.b[2] = __float2bfloat16(v.z);
        H.b[3] = __float2bfloat16(v.w);
        L.b[0] = __float2bfloat16(v.x - __bfloat162float(H.b[0]));
        L.b[1] = __float2bfloat16(v.y - __bfloat162float(H.b[1]));
        L.b[2] = __float2bfloat16(v.z - __bfloat162float(H.b[2]));
        L.b[3] = __float2bfloat16(v.w - __bfloat162float(H.b[3]));
        *(uint2*)(xh + 4 * (size_t)i) = H.u;
        *(uint2*)(xl + 4 * (size_t)i) = L.u;
    }
}

// transpose + split: Wt[n][k] = W[k][n]   (z-dim selects which of 4 weights)
__global__ __launch_bounds__(256)
void conv_w4(const float* __restrict__ W0, const float* __restrict__ W1,
             const float* __restrict__ W2, const float* __restrict__ W3,
             __nv_bfloat16* __restrict__ Th, __nv_bfloat16* __restrict__ Tl)
{
    const float* Ws[4] = {W0, W1, W2, W3};
    const float* W = Ws[blockIdx.z];
    __nv_bfloat16* th = Th + (size_t)blockIdx.z * FF * FF;
    __nv_bfloat16* tl = Tl + (size_t)blockIdx.z * FF * FF;

    __shared__ float t[32][33];
    const int bx = blockIdx.x * 32, by = blockIdx.y * 32;
    const int tx = threadIdx.x, ty = threadIdx.y;
    #pragma unroll
    for (int i = ty; i < 32; i += 8)
        t[i][tx] = W[(size_t)(by + i) * FF + bx + tx];
    __syncthreads();
    #pragma unroll
    for (int i = ty; i < 32; i += 8) {
        float v = t[tx][i];   // = W[by+tx][bx+i]
        __nv_bfloat16 h = __float2bfloat16(v);
        __nv_bfloat16 l = __float2bfloat16(v - __bfloat162float(h));
        size_t off = (size_t)(bx + i) * FF + by + tx;
        th[off] = h;
        tl[off] = l;
    }
}

// ---------------------------------------------------------------------------
// kv partial: per (h, b, split) compute 64x64 K^T V over SEQ_PER_SPLIT rows
// ---------------------------------------------------------------------------
__global__ __launch_bounds__(256)
void kv_partial_kernel()
{
    const int h = blockIdx.x;
    const int b = blockIdx.y;
    const int s = blockIdx.z;
    const int tid = threadIdx.x;

    __shared__ float ks[32][DH];
    __shared__ float vs[32][DH];

    const int tx = tid & 15;
    const int ty = tid >> 4;

    float acc[4][4];
    #pragma unroll
    for (int i = 0; i < 4; i++)
        #pragma unroll
        for (int j = 0; j < 4; j++) acc[i][j] = 0.0f;
    float ksum_part = 0.0f;

    const size_t base = ((size_t)b * SEQ + (size_t)s * SEQ_PER_SPLIT) * FF + h * DH;
    const int lrow = tid >> 4;
    const int lcol = (tid & 15) * 4;

    const int nchunks = SEQ_PER_SPLIT / 32;
    for (int c = 0; c < nchunks; c++) {
        const size_t cb = base + (size_t)c * 32 * FF;
        #pragma unroll
        for (int i = 0; i < 2; i++) {
            int r = lrow + i * 16;
            *(float4*)&ks[r][lcol] = *(const float4*)(g_k + cb + (size_t)r * FF + lcol);
            *(float4*)&vs[r][lcol] = *(const float4*)(g_v + cb + (size_t)r * FF + lcol);
        }
        __syncthreads();
        #pragma unroll 4
        for (int n = 0; n < 32; n++) {
            float a[4], bb[4];
            #pragma unroll
            for (int i = 0; i < 4; i++) a[i]  = ks[n][ty * 4 + i];
            #pragma unroll
            for (int j = 0; j < 4; j++) bb[j] = vs[n][tx * 4 + j];
            #pragma unroll
            for (int i = 0; i < 4; i++)
                #pragma unroll
                for (int j = 0; j < 4; j++)
                    acc[i][j] += a[i] * bb[j];
        }
        if (tid < DH) {
            float sum = 0.0f;
            #pragma unroll
            for (int n = 0; n < 32; n++) sum += ks[n][tid];
            ksum_part += sum;
        }
        __syncthreads();
    }

    const int hb = b * NH + h;
    float* kvout = g_kvp + ((size_t)s * BH + hb) * DH * DH;
    #pragma unroll
    for (int i = 0; i < 4; i++)
        #pragma unroll
        for (int j = 0; j < 4; j++)
            kvout[(ty * 4 + i) * DH + tx * 4 + j] = acc[i][j];
    if (tid < DH)
        g_ksp[((size_t)s * BH + hb) * DH + tid] = ksum_part;
}

__global__ __launch_bounds__(256)
void kv_reduce_kernel()
{
    const int idx = blockIdx.x * 256 + threadIdx.x;
    if (idx < BH * DH * DH) {
        float s = 0.0f;
        #pragma unroll
        for (int p = 0; p < KV_SPLITS; p++) s += g_kvp[(size_t)p * (BH * DH * DH) + idx];
        g_kv[idx] = s;
    }
    if (idx < BH * DH) {
        float s = 0.0f;
        #pragma unroll
        for (int p = 0; p < KV_SPLITS; p++) s += g_ksp[(size_t)p * (BH * DH) + idx];
        g_ks[idx] = s;
    }
}

// ---------------------------------------------------------------------------
// attention out: normed = (q @ kv) * 1/(q . ksum); writes hi/lo bf16
// ---------------------------------------------------------------------------
__global__ __launch_bounds__(256)
void attn_out_kernel()
{
    const int c = blockIdx.x;
    const int h = blockIdx.y;
    const int b = blockIdx.z;
    const int tid = threadIdx.x;
    const int hb = b * NH + h;

    __shared__ float kvs[DH * DH];
    __shared__ float kss[DH];
    __shared__ float qs[32][DH];
    __shared__ float zs[32];

    {
        const float4* kv4 = (const float4*)(g_kv + (size_t)hb * DH * DH);
        float4* s4 = (float4*)kvs;
        #pragma unroll
        for (int i = 0; i < 4; i++) s4[tid + i * 256] = kv4[tid + i * 256];
        if (tid < DH) kss[tid] = g_ks[(size_t)hb * DH + tid];
    }
    const size_t qbase = ((size_t)b * SEQ + (size_t)c * 32) * FF + h * DH;
    {
        const int lrow = tid >> 4, lcol = (tid & 15) * 4;
        #pragma unroll
        for (int i = 0; i < 2; i++) {
            int r = lrow + i * 16;
            *(float4*)&qs[r][lcol] = *(const float4*)(g_q + qbase + (size_t)r * FF + lcol);
        }
    }
    __syncthreads();

    const int r  = tid >> 3;
    const int eg = tid & 7;

    if (eg == 0) {
        float s = 0.0f;
        #pragma unroll
        for (int dd = 0; dd < DH; dd++) s += qs[r][dd] * kss[dd];
        zs[r] = 1.0f / s;
    }
    __syncthreads();

    float4 oa = make_float4(0, 0, 0, 0), ob = make_float4(0, 0, 0, 0);
    const float4* kvrow = ((const float4*)kvs) + eg * 2;
    #pragma unroll
    for (int dd = 0; dd < DH; dd++) {
        float qv = qs[r][dd];
        float4 ka = kvrow[dd * 16];
        float4 kb = kvrow[dd * 16 + 1];
        oa.x += qv * ka.x; oa.y += qv * ka.y; oa.z += qv * ka.z; oa.w += qv * ka.w;
        ob.x += qv * kb.x; ob.y += qv * kb.y; ob.z += qv * kb.z; ob.w += qv * kb.w;
    }
    const float z = zs[r];
    float o[8] = { oa.x * z, oa.y * z, oa.z * z, oa.w * z,
                   ob.x * z, ob.y * z, ob.z * z, ob.w * z };

    union { __nv_bfloat16 b2[8]; uint4 u; } H, L;
    #pragma unroll
    for (int j = 0; j < 8; j++) {
        H.b2[j] = __float2bfloat16(o[j]);
        L.b2[j] = __float2bfloat16(o[j] - __bfloat162float(H.b2[j]));
    }
    const size_t off = ((size_t)b * SEQ + (size_t)c * 32 + r) * FF + h * DH + eg * 8;
    *(uint4*)(g_nh + off) = H.u;
    *(uint4*)(g_nl + off) = L.u;
}

// ---------------------------------------------------------------------------
// launch
// ---------------------------------------------------------------------------
extern "C" void kernel_launch(void* const* d_in, const int* in_sizes, int n_in,
                              void* d_out, int out_size)
{
    const float* x  = (const float*)d_in[0];
    const float* Wq = (const float*)d_in[1];
    const float* bq = (const float*)d_in[2];
    const float* Wk = (const float*)d_in[3];
    const float* bk = (const float*)d_in[4];
    const float* Wv = (const float*)d_in[5];
    const float* bv = (const float*)d_in[6];
    const float* Wo = (const float*)d_in[7];
    const float* bo = (const float*)d_in[8];
    float* out = (float*)d_out;

    __nv_bfloat16 *pxh, *pxl, *pnh, *pnl, *pwh, *pwl;
    float *pq, *pk, *pv;
    cudaGetSymbolAddress((void**)&pxh, g_xh);
    cudaGetSymbolAddress((void**)&pxl, g_xl);
    cudaGetSymbolAddress((void**)&pnh, g_nh);
    cudaGetSymbolAddress((void**)&pnl, g_nl);
    cudaGetSymbolAddress((void**)&pwh, g_wh);
    cudaGetSymbolAddress((void**)&pwl, g_wl);
    cudaGetSymbolAddress((void**)&pq,  g_q);
    cudaGetSymbolAddress((void**)&pk,  g_k);
    cudaGetSymbolAddress((void**)&pv,  g_v);

    static bool attr_done = false;
    if (!attr_done) {
        cudaFuncSetAttribute(mma_gemm<true>,  cudaFuncAttributeMaxDynamicSharedMemorySize, SMEM_DYN);
        cudaFuncSetAttribute(mma_gemm<false>, cudaFuncAttributeMaxDynamicSharedMemorySize, SMEM_DYN);
        attr_done = true;
    }

    // weight transpose + split (all 4 in one launch)
    conv_w4<<<dim3(FF / 32, FF / 32, 4), dim3(32, 8)>>>(Wq, Wk, Wv, Wo, pwh, pwl);

    // x split
    conv_x<<<2048, 256>>>((const float4*)x, pxh, pxl, MROWS * FF / 4);

    dim3 ggrid(FF / GBN, MROWS / GBM);   // (6, 128)
    // projections (tensor cores via mma.sync)
    mma_gemm<true ><<<ggrid, 512, SMEM_DYN>>>(pxh, pxl, pwh + 0 * (size_t)FF * FF, pwl + 0 * (size_t)FF * FF, bq, pq);
    mma_gemm<true ><<<ggrid, 512, SMEM_DYN>>>(pxh, pxl, pwh + 1 * (size_t)FF * FF, pwl + 1 * (size_t)FF * FF, bk, pk);
    mma_gemm<false><<<ggrid, 512, SMEM_DYN>>>(pxh, pxl, pwh + 2 * (size_t)FF * FF, pwl + 2 * (size_t)FF * FF, bv, pv);

    // kv summary + reduce
    kv_partial_kernel<<<dim3(NH, BATCH, KV_SPLITS), 256>>>();
    kv_reduce_kernel<<<(BH * DH * DH + 255) / 256, 256>>>();

    // attention output (writes hi/lo bf16)
    attn_out_kernel<<<dim3(SEQ / 32, NH, BATCH), 256>>>();

    // output projection
    mma_gemm<false><<<ggrid, 512, SMEM_DYN>>>(pnh, pnl, pwh + 3 * (size_t)FF * FF, pwl + 3 * (size_t)FF * FF, bo, out);
}

// round 5
// speedup vs baseline: 2.8204x; 1.5514x over previous
#include <cuda_runtime.h>
#include <cuda_fp16.h>
#include <math.h>
#include <cstdint>

// ---------------------------------------------------------------------------
// Problem dims (fixed by the dataset)
// ---------------------------------------------------------------------------
#define BATCH 4
#define SEQ   4096
#define FF    768
#define NH    12
#define DH    64
#define MROWS (BATCH*SEQ)     // 16384
#define BH    (BATCH*NH)      // 48
#define KV_SPLITS 32
#define SEQ_PER_SPLIT (SEQ/KV_SPLITS)   // 128

// ---------------------------------------------------------------------------
// Static device scratch (no runtime allocation allowed)
// ---------------------------------------------------------------------------
__device__ __half  g_x [MROWS * FF];        // x in fp16 (single)
__device__ float   g_q [MROWS * FF];
__device__ float   g_k [MROWS * FF];
__device__ float   g_v [MROWS * FF];
__device__ __half  g_n [MROWS * FF];        // attn output in fp16 (single)
__device__ __half  g_wh[4][FF * FF];        // transposed weights, hi  [n][k]
__device__ __half  g_wl[4][FF * FF];        // transposed weights, lo
__device__ float g_kvp[KV_SPLITS * BH * DH * DH];
__device__ float g_ksp[KV_SPLITS * BH * DH];
__device__ float g_kv [BH * DH * DH];
__device__ float g_ks [BH * DH];

// ---------------------------------------------------------------------------
// PTX helpers (baseline sm_80-class instructions only)
// ---------------------------------------------------------------------------
__device__ __forceinline__ uint32_t smem_u32(const void* p) {
    uint32_t a;
    asm("{ .reg .u64 t; cvta.to.shared.u64 t, %1; cvt.u32.u64 %0, t; }"
        : "=r"(a) : "l"(p));
    return a;
}

__device__ __forceinline__ void cp16(uint32_t dst, const void* src) {
    asm volatile("cp.async.cg.shared.global [%0], [%1], 16;" :: "r"(dst), "l"(src));
}
#define CP_COMMIT() asm volatile("cp.async.commit_group;" ::: "memory")
template <int N>
__device__ __forceinline__ void cp_wait() {
    asm volatile("cp.async.wait_group %0;" :: "n"(N) : "memory");
}

__device__ __forceinline__ void ldsm_x4(uint32_t* r, uint32_t addr) {
    asm volatile("ldmatrix.sync.aligned.m8n8.x4.shared.b16 {%0,%1,%2,%3}, [%4];"
                 : "=r"(r[0]), "=r"(r[1]), "=r"(r[2]), "=r"(r[3]) : "r"(addr));
}

// D += A * B   (m16n8k16, fp16 in, fp32 accum)
__device__ __forceinline__ void mma16816(float* d, const uint32_t* a, const uint32_t* b) {
    asm volatile(
        "mma.sync.aligned.m16n8k16.row.col.f32.f16.f16.f32 "
        "{%0,%1,%2,%3}, {%4,%5,%6,%7}, {%8,%9}, {%0,%1,%2,%3};"
        : "+f"(d[0]), "+f"(d[1]), "+f"(d[2]), "+f"(d[3])
        : "r"(a[0]), "r"(a[1]), "r"(a[2]), "r"(a[3]), "r"(b[0]), "r"(b[1]));
}

// ---------------------------------------------------------------------------
// mma_gemm: C[16384,768] = A[M,K] @ (Wh+Wl)[N,K]^T + bias   (A single fp16)
// CTA tile 128x256, BK=64, 512 threads = 16 warps (2 M x 8 N), warp 64x32.
// 128B smem rows + XOR-8 chunk swizzle -> conflict-free ldmatrix & stores.
// 2-stage cp.async double buffer (prefetch distance = 1 full K-iter).
// ---------------------------------------------------------------------------
#define GBM 128
#define GBN 256
#define GBK 64
#define A_OFF  0
#define A_BYTES  (128 * 128)        // 16 KB
#define BH_OFF A_BYTES
#define B_BYTES  (256 * 128)        // 32 KB
#define BL_OFF (BH_OFF + B_BYTES)
#define STAGE_BYTES (A_BYTES + 2 * B_BYTES)   // 80 KB
#define SMEM_DYN (2 * STAGE_BYTES)            // 160 KB
#define NIT (FF / GBK)              // 12

template <bool PHI>
__device__ __forceinline__ float ep(float v) {
    if (PHI) return v > 0.0f ? v + 1.0f : expf(v);   // elu(v)+1
    return v;
}

// 512 threads fill one 80KB stage: A 2 chunks/thread, Bh/Bl 4 chunks/thread.
__device__ __forceinline__ void load_stage(uint32_t st,
        const __half* __restrict__ A, const __half* __restrict__ Bh,
        const __half* __restrict__ Bl, int brow, int bcol, int kbase, int tid)
{
    #pragma unroll
    for (int i = 0; i < 2; i++) {
        const int cid = tid + i * 512;        // 0..1023
        const int r = cid >> 3, c = cid & 7;
        const uint32_t d = st + A_OFF + (uint32_t)r * 128 + (uint32_t)((c ^ (r & 7)) << 4);
        cp16(d, A + (size_t)(brow + r) * FF + kbase + c * 8);
    }
    #pragma unroll
    for (int i = 0; i < 4; i++) {
        const int cid = tid + i * 512;        // 0..2047
        const int r = cid >> 3, c = cid & 7;
        const uint32_t sw = (uint32_t)r * 128 + (uint32_t)((c ^ (r & 7)) << 4);
        const size_t go = (size_t)(bcol + r) * FF + kbase + c * 8;
        cp16(st + BH_OFF + sw, Bh + go);
        cp16(st + BL_OFF + sw, Bl + go);
    }
}

template <bool PHI>
__global__ __launch_bounds__(512, 1)
void mma_gemm(const __half* __restrict__ A, const __half* __restrict__ Bh,
              const __half* __restrict__ Bl, const float* __restrict__ bias,
              float* __restrict__ C)
{
    extern __shared__ char dsm[];
    const uint32_t sb = smem_u32(dsm);

    const int tid  = threadIdx.x;
    const int warp = tid >> 5;
    const int lane = tid & 31;
    const int wm   = warp & 1;        // 0..1 -> M offset 64*wm
    const int wn   = warp >> 1;       // 0..7 -> N offset 32*wn
    const int brow = blockIdx.y * GBM;
    const int bcol = blockIdx.x * GBN;

    float acc[4][4][4];
    #pragma unroll
    for (int i = 0; i < 4; i++)
        #pragma unroll
        for (int j = 0; j < 4; j++)
            #pragma unroll
            for (int q = 0; q < 4; q++) acc[i][j][q] = 0.0f;

    load_stage(sb, A, Bh, Bl, brow, bcol, 0, tid);
    CP_COMMIT();

    const int a_row0 = wm * 64 + (lane & 15);   // + mf*16
    const int b_row0 = wn * 32 + (lane & 15);   // + bq*16
    const int khalf  = lane >> 4;               // 0/1 -> k8 half

    for (int it = 0; it < NIT; it++) {
        if (it + 1 < NIT) {
            load_stage(sb + (uint32_t)((it + 1) & 1) * STAGE_BYTES,
                       A, Bh, Bl, brow, bcol, (it + 1) * GBK, tid);
            CP_COMMIT();
            cp_wait<1>();
        } else {
            cp_wait<0>();
        }
        __syncthreads();

        const uint32_t st = sb + (uint32_t)(it & 1) * STAGE_BYTES;

        #pragma unroll
        for (int ks = 0; ks < 4; ks++) {
            const int chunk = ks * 2 + khalf;     // 16B chunk index 0..7
            uint32_t Af[4][4], Bhf[4][2], Blf[4][2];
            #pragma unroll
            for (int mf = 0; mf < 4; mf++) {
                const int row = a_row0 + mf * 16;
                const uint32_t ad = st + A_OFF + (uint32_t)row * 128
                                  + (uint32_t)((chunk ^ (row & 7)) << 4);
                ldsm_x4(Af[mf], ad);
            }
            #pragma unroll
            for (int bq = 0; bq < 2; bq++) {
                const int row = b_row0 + bq * 16;
                const uint32_t off = (uint32_t)row * 128
                                   + (uint32_t)((chunk ^ (row & 7)) << 4);
                uint32_t t[4];
                ldsm_x4(t, st + BH_OFF + off);
                Bhf[bq * 2][0] = t[0];     Bhf[bq * 2][1] = t[2];
                Bhf[bq * 2 + 1][0] = t[1]; Bhf[bq * 2 + 1][1] = t[3];
                ldsm_x4(t, st + BL_OFF + off);
                Blf[bq * 2][0] = t[0];     Blf[bq * 2][1] = t[2];
                Blf[bq * 2 + 1][0] = t[1]; Blf[bq * 2 + 1][1] = t[3];
            }
            #pragma unroll
            for (int mf = 0; mf < 4; mf++)
                #pragma unroll
                for (int nf = 0; nf < 4; nf++) {
                    mma16816(acc[mf][nf], Af[mf], Bhf[nf]);
                    mma16816(acc[mf][nf], Af[mf], Blf[nf]);
                }
        }
        __syncthreads();
    }

    // epilogue: bias + optional phi
    #pragma unroll
    for (int nf = 0; nf < 4; nf++) {
        const int col = bcol + wn * 32 + nf * 8 + 2 * (lane & 3);
        const float b0 = bias[col], b1 = bias[col + 1];
        #pragma unroll
        for (int mf = 0; mf < 4; mf++) {
            const int r0 = brow + wm * 64 + mf * 16 + (lane >> 2);
            float2 v;
            v.x = ep<PHI>(acc[mf][nf][0] + b0);
            v.y = ep<PHI>(acc[mf][nf][1] + b1);
            *(float2*)(C + (size_t)r0 * FF + col) = v;
            v.x = ep<PHI>(acc[mf][nf][2] + b0);
            v.y = ep<PHI>(acc[mf][nf][3] + b1);
            *(float2*)(C + (size_t)(r0 + 8) * FF + col) = v;
        }
    }
}

// ---------------------------------------------------------------------------
// conversions
// ---------------------------------------------------------------------------
__global__ __launch_bounds__(256)
void conv_x(const float4* __restrict__ in, __half* __restrict__ x16, int n4)
{
    for (int i = blockIdx.x * 256 + threadIdx.x; i < n4; i += gridDim.x * 256) {
        float4 v = in[i];
        union { __half h[4]; uint2 u; } H;
        H.h[0] = __float2half_rn(v.x);
        H.h[1] = __float2half_rn(v.y);
        H.h[2] = __float2half_rn(v.z);
        H.h[3] = __float2half_rn(v.w);
        *(uint2*)(x16 + 4 * (size_t)i) = H.u;
    }
}

// transpose + hi/lo split: Wt[n][k] = W[k][n]   (z selects which weight)
__global__ __launch_bounds__(256)
void conv_w4(const float* __restrict__ W0, const float* __restrict__ W1,
             const float* __restrict__ W2, const float* __restrict__ W3,
             __half* __restrict__ Th, __half* __restrict__ Tl)
{
    const float* Ws[4] = {W0, W1, W2, W3};
    const float* W = Ws[blockIdx.z];
    __half* th = Th + (size_t)blockIdx.z * FF * FF;
    __half* tl = Tl + (size_t)blockIdx.z * FF * FF;

    __shared__ float t[32][33];
    const int bx = blockIdx.x * 32, by = blockIdx.y * 32;
    const int tx = threadIdx.x, ty = threadIdx.y;
    #pragma unroll
    for (int i = ty; i < 32; i += 8)
        t[i][tx] = W[(size_t)(by + i) * FF + bx + tx];
    __syncthreads();
    #pragma unroll
    for (int i = ty; i < 32; i += 8) {
        float v = t[tx][i];   // = W[by+tx][bx+i]
        __half h = __float2half_rn(v);
        __half l = __float2half_rn(v - __half2float(h));
        size_t off = (size_t)(bx + i) * FF + by + tx;
        th[off] = h;
        tl[off] = l;
    }
}

// ---------------------------------------------------------------------------
// kv partial: per (h, b, split) compute 64x64 K^T V over SEQ_PER_SPLIT rows
// ---------------------------------------------------------------------------
__global__ __launch_bounds__(256)
void kv_partial_kernel()
{
    const int h = blockIdx.x;
    const int b = blockIdx.y;
    const int s = blockIdx.z;
    const int tid = threadIdx.x;

    __shared__ float ks[32][DH];
    __shared__ float vs[32][DH];

    const int tx = tid & 15;
    const int ty = tid >> 4;

    float acc[4][4];
    #pragma unroll
    for (int i = 0; i < 4; i++)
        #pragma unroll
        for (int j = 0; j < 4; j++) acc[i][j] = 0.0f;
    float ksum_part = 0.0f;

    const size_t base = ((size_t)b * SEQ + (size_t)s * SEQ_PER_SPLIT) * FF + h * DH;
    const int lrow = tid >> 4;
    const int lcol = (tid & 15) * 4;

    const int nchunks = SEQ_PER_SPLIT / 32;
    for (int c = 0; c < nchunks; c++) {
        const size_t cb = base + (size_t)c * 32 * FF;
        #pragma unroll
        for (int i = 0; i < 2; i++) {
            int r = lrow + i * 16;
            *(float4*)&ks[r][lcol] = *(const float4*)(g_k + cb + (size_t)r * FF + lcol);
            *(float4*)&vs[r][lcol] = *(const float4*)(g_v + cb + (size_t)r * FF + lcol);
        }
        __syncthreads();
        #pragma unroll 4
        for (int n = 0; n < 32; n++) {
            float a[4], bb[4];
            #pragma unroll
            for (int i = 0; i < 4; i++) a[i]  = ks[n][ty * 4 + i];
            #pragma unroll
            for (int j = 0; j < 4; j++) bb[j] = vs[n][tx * 4 + j];
            #pragma unroll
            for (int i = 0; i < 4; i++)
                #pragma unroll
                for (int j = 0; j < 4; j++)
                    acc[i][j] += a[i] * bb[j];
        }
        if (tid < DH) {
            float sum = 0.0f;
            #pragma unroll
            for (int n = 0; n < 32; n++) sum += ks[n][tid];
            ksum_part += sum;
        }
        __syncthreads();
    }

    const int hb = b * NH + h;
    float* kvout = g_kvp + ((size_t)s * BH + hb) * DH * DH;
    #pragma unroll
    for (int i = 0; i < 4; i++)
        #pragma unroll
        for (int j = 0; j < 4; j++)
            kvout[(ty * 4 + i) * DH + tx * 4 + j] = acc[i][j];
    if (tid < DH)
        g_ksp[((size_t)s * BH + hb) * DH + tid] = ksum_part;
}

__global__ __launch_bounds__(256)
void kv_reduce_kernel()
{
    const int idx = blockIdx.x * 256 + threadIdx.x;
    if (idx < BH * DH * DH) {
        float s = 0.0f;
        #pragma unroll
        for (int p = 0; p < KV_SPLITS; p++) s += g_kvp[(size_t)p * (BH * DH * DH) + idx];
        g_kv[idx] = s;
    }
    if (idx < BH * DH) {
        float s = 0.0f;
        #pragma unroll
        for (int p = 0; p < KV_SPLITS; p++) s += g_ksp[(size_t)p * (BH * DH) + idx];
        g_ks[idx] = s;
    }
}

// ---------------------------------------------------------------------------
// attention out: normed = (q @ kv) * 1/(q . ksum); writes fp16
// ---------------------------------------------------------------------------
__global__ __launch_bounds__(256)
void attn_out_kernel()
{
    const int c = blockIdx.x;
    const int h = blockIdx.y;
    const int b = blockIdx.z;
    const int tid = threadIdx.x;
    const int hb = b * NH + h;

    __shared__ float kvs[DH * DH];
    __shared__ float kss[DH];
    __shared__ float qs[32][DH];
    __shared__ float zs[32];

    {
        const float4* kv4 = (const float4*)(g_kv + (size_t)hb * DH * DH);
        float4* s4 = (float4*)kvs;
        #pragma unroll
        for (int i = 0; i < 4; i++) s4[tid + i * 256] = kv4[tid + i * 256];
        if (tid < DH) kss[tid] = g_ks[(size_t)hb * DH + tid];
    }
    const size_t qbase = ((size_t)b * SEQ + (size_t)c * 32) * FF + h * DH;
    {
        const int lrow = tid >> 4, lcol = (tid & 15) * 4;
        #pragma unroll
        for (int i = 0; i < 2; i++) {
            int r = lrow + i * 16;
            *(float4*)&qs[r][lcol] = *(const float4*)(g_q + qbase + (size_t)r * FF + lcol);
        }
    }
    __syncthreads();

    const int r  = tid >> 3;
    const int eg = tid & 7;

    if (eg == 0) {
        float s = 0.0f;
        #pragma unroll
        for (int dd = 0; dd < DH; dd++) s += qs[r][dd] * kss[dd];
        zs[r] = 1.0f / s;
    }
    __syncthreads();

    float4 oa = make_float4(0, 0, 0, 0), ob = make_float4(0, 0, 0, 0);
    const float4* kvrow = ((const float4*)kvs) + eg * 2;
    #pragma unroll
    for (int dd = 0; dd < DH; dd++) {
        float qv = qs[r][dd];
        float4 ka = kvrow[dd * 16];
        float4 kb = kvrow[dd * 16 + 1];
        oa.x += qv * ka.x; oa.y += qv * ka.y; oa.z += qv * ka.z; oa.w += qv * ka.w;
        ob.x += qv * kb.x; ob.y += qv * kb.y; ob.z += qv * kb.z; ob.w += qv * kb.w;
    }
    const float z = zs[r];
    float o[8] = { oa.x * z, oa.y * z, oa.z * z, oa.w * z,
                   ob.x * z, ob.y * z, ob.z * z, ob.w * z };

    union { __half h2[8]; uint4 u; } H;
    #pragma unroll
    for (int j = 0; j < 8; j++) H.h2[j] = __float2half_rn(o[j]);
    const size_t off = ((size_t)b * SEQ + (size_t)c * 32 + r) * FF + h * DH + eg * 8;
    *(uint4*)(g_n + off) = H.u;
}

// ---------------------------------------------------------------------------
// launch
// ---------------------------------------------------------------------------
extern "C" void kernel_launch(void* const* d_in, const int* in_sizes, int n_in,
                              void* d_out, int out_size)
{
    const float* x  = (const float*)d_in[0];
    const float* Wq = (const float*)d_in[1];
    const float* bq = (const float*)d_in[2];
    const float* Wk = (const float*)d_in[3];
    const float* bk = (const float*)d_in[4];
    const float* Wv = (const float*)d_in[5];
    const float* bv = (const float*)d_in[6];
    const float* Wo = (const float*)d_in[7];
    const float* bo = (const float*)d_in[8];
    float* out = (float*)d_out;

    __half *px, *pn, *pwh, *pwl;
    float *pq, *pk, *pv;
    cudaGetSymbolAddress((void**)&px,  g_x);
    cudaGetSymbolAddress((void**)&pn,  g_n);
    cudaGetSymbolAddress((void**)&pwh, g_wh);
    cudaGetSymbolAddress((void**)&pwl, g_wl);
    cudaGetSymbolAddress((void**)&pq,  g_q);
    cudaGetSymbolAddress((void**)&pk,  g_k);
    cudaGetSymbolAddress((void**)&pv,  g_v);

    cudaFuncSetAttribute(mma_gemm<true>,  cudaFuncAttributeMaxDynamicSharedMemorySize, SMEM_DYN);
    cudaFuncSetAttribute(mma_gemm<false>, cudaFuncAttributeMaxDynamicSharedMemorySize, SMEM_DYN);

    // weight transpose + split (all 4 in one launch)
    conv_w4<<<dim3(FF / 32, FF / 32, 4), dim3(32, 8)>>>(Wq, Wk, Wv, Wo, pwh, pwl);

    // x -> fp16
    conv_x<<<2048, 256>>>((const float4*)x, px, MROWS * FF / 4);

    dim3 ggrid(FF / GBN, MROWS / GBM);   // (3, 128)
    // projections (tensor cores via mma.sync)
    mma_gemm<true ><<<ggrid, 512, SMEM_DYN>>>(px, pwh + 0 * (size_t)FF * FF, pwl + 0 * (size_t)FF * FF, bq, pq);
    mma_gemm<true ><<<ggrid, 512, SMEM_DYN>>>(px, pwh + 1 * (size_t)FF * FF, pwl + 1 * (size_t)FF * FF, bk, pk);
    mma_gemm<false><<<ggrid, 512, SMEM_DYN>>>(px, pwh + 2 * (size_t)FF * FF, pwl + 2 * (size_t)FF * FF, bv, pv);

    // kv summary + reduce
    kv_partial_kernel<<<dim3(NH, BATCH, KV_SPLITS), 256>>>();
    kv_reduce_kernel<<<(BH * DH * DH + 255) / 256, 256>>>();

    // attention output (writes fp16)
    attn_out_kernel<<<dim3(SEQ / 32, NH, BATCH), 256>>>();

    // output projection
    mma_gemm<false><<<ggrid, 512, SMEM_DYN>>>(pn, pwh + 3 * (size_t)FF * FF, pwl + 3 * (size_t)FF * FF, bo, out);
}

// round 6
// speedup vs baseline: 2.8728x; 1.0186x over previous
#include <cuda_runtime.h>
#include <cuda_fp16.h>
#include <math.h>
#include <cstdint>

// ---------------------------------------------------------------------------
// Problem dims (fixed by the dataset)
// ---------------------------------------------------------------------------
#define BATCH 4
#define SEQ   4096
#define FF    768
#define NH    12
#define DH    64
#define MROWS (BATCH*SEQ)     // 16384
#define BH    (BATCH*NH)      // 48
#define KV_SPLITS 32
#define SEQ_PER_SPLIT (SEQ/KV_SPLITS)   // 128

// ---------------------------------------------------------------------------
// Static device scratch (no runtime allocation allowed)
// ---------------------------------------------------------------------------
__device__ __half  g_x [MROWS * FF];        // x in fp16
__device__ __half  g_q [MROWS * FF];        // q = phi(xWq+b) fp16
__device__ __half  g_k [MROWS * FF];        // k fp16
__device__ __half  g_v [MROWS * FF];        // v fp16
__device__ __half  g_n [MROWS * FF];        // attn output fp16
__device__ __half  g_wh[4][FF * FF];        // transposed weights, hi  [n][k]
__device__ __half  g_wl[4][FF * FF];        // transposed weights, lo
__device__ float g_kvp[KV_SPLITS * BH * DH * DH];
__device__ float g_ksp[KV_SPLITS * BH * DH];
__device__ float g_kv [BH * DH * DH];
__device__ float g_ks [BH * DH];

// ---------------------------------------------------------------------------
// PTX helpers (baseline sm_80-class instructions only)
// ---------------------------------------------------------------------------
__device__ __forceinline__ uint32_t smem_u32(const void* p) {
    uint32_t a;
    asm("{ .reg .u64 t; cvta.to.shared.u64 t, %1; cvt.u32.u64 %0, t; }"
        : "=r"(a) : "l"(p));
    return a;
}

__device__ __forceinline__ void cp16(uint32_t dst, const void* src) {
    asm volatile("cp.async.cg.shared.global [%0], [%1], 16;" :: "r"(dst), "l"(src));
}
#define CP_COMMIT() asm volatile("cp.async.commit_group;" ::: "memory")
template <int N>
__device__ __forceinline__ void cp_wait() {
    asm volatile("cp.async.wait_group %0;" :: "n"(N) : "memory");
}

__device__ __forceinline__ void ldsm_x4(uint32_t* r, uint32_t addr) {
    asm volatile("ldmatrix.sync.aligned.m8n8.x4.shared.b16 {%0,%1,%2,%3}, [%4];"
                 : "=r"(r[0]), "=r"(r[1]), "=r"(r[2]), "=r"(r[3]) : "r"(addr));
}

// D += A * B   (m16n8k16, fp16 in, fp32 accum)
__device__ __forceinline__ void mma16816(float* d, const uint32_t* a, const uint32_t* b) {
    asm volatile(
        "mma.sync.aligned.m16n8k16.row.col.f32.f16.f16.f32 "
        "{%0,%1,%2,%3}, {%4,%5,%6,%7}, {%8,%9}, {%0,%1,%2,%3};"
        : "+f"(d[0]), "+f"(d[1]), "+f"(d[2]), "+f"(d[3])
        : "r"(a[0]), "r"(a[1]), "r"(a[2]), "r"(a[3]), "r"(b[0]), "r"(b[1]));
}

// ---------------------------------------------------------------------------
// mma_gemm: C[16384,768] = A[M,K] @ (Wh+Wl)[N,K]^T + bias   (A single fp16)
// CTA tile 128x128, BK=64, 256 threads = 8 warps (2 M x 4 N), warp 64x32.
// 128B smem rows + XOR-8 chunk swizzle -> conflict-free ldmatrix & stores.
// 2-stage cp.async double buffer; 2 CTAs/SM (96KB smem, <=128 regs).
// ---------------------------------------------------------------------------
#define GBM 128
#define GBN 128
#define GBK 64
#define A_OFF  0
#define A_BYTES  (128 * 128)        // 16 KB
#define BH_OFF A_BYTES
#define B_BYTES  (128 * 128)        // 16 KB
#define BL_OFF (BH_OFF + B_BYTES)
#define STAGE_BYTES (A_BYTES + 2 * B_BYTES)   // 48 KB
#define SMEM_DYN (2 * STAGE_BYTES)            // 96 KB
#define NIT (FF / GBK)              // 12

template <bool PHI>
__device__ __forceinline__ float ep(float v) {
    if (PHI) return v > 0.0f ? v + 1.0f : expf(v);   // elu(v)+1
    return v;
}

__device__ __forceinline__ void store2(float* C, size_t idx, float a, float b) {
    *(float2*)(C + idx) = make_float2(a, b);
}
__device__ __forceinline__ void store2(__half* C, size_t idx, float a, float b) {
    *(__half2*)(C + idx) = __floats2half2_rn(a, b);
}

// 256 threads fill one 48KB stage: 4 chunks/thread per matrix (A, Bh, Bl).
__device__ __forceinline__ void load_stage(uint32_t st,
        const __half* __restrict__ A, const __half* __restrict__ Bh,
        const __half* __restrict__ Bl, int brow, int bcol, int kbase, int tid)
{
    #pragma unroll
    for (int i = 0; i < 4; i++) {
        const int cid = tid + i * 256;        // 0..1023
        const int r = cid >> 3, c = cid & 7;
        const uint32_t sw = (uint32_t)r * 128 + (uint32_t)((c ^ (r & 7)) << 4);
        const size_t goA = (size_t)(brow + r) * FF + kbase + c * 8;
        const size_t goB = (size_t)(bcol + r) * FF + kbase + c * 8;
        cp16(st + A_OFF + sw, A + goA);
        cp16(st + BH_OFF + sw, Bh + goB);
        cp16(st + BL_OFF + sw, Bl + goB);
    }
}

template <bool PHI, typename OutT>
__global__ __launch_bounds__(256, 2)
void mma_gemm(const __half* __restrict__ A, const __half* __restrict__ Bh,
              const __half* __restrict__ Bl, const float* __restrict__ bias,
              OutT* __restrict__ C)
{
    extern __shared__ char dsm[];
    const uint32_t sb = smem_u32(dsm);

    const int tid  = threadIdx.x;
    const int warp = tid >> 5;
    const int lane = tid & 31;
    const int wm   = warp & 1;        // 0..1 -> M offset 64*wm
    const int wn   = warp >> 1;       // 0..3 -> N offset 32*wn
    const int brow = blockIdx.y * GBM;
    const int bcol = blockIdx.x * GBN;

    float acc[4][4][4];
    #pragma unroll
    for (int i = 0; i < 4; i++)
        #pragma unroll
        for (int j = 0; j < 4; j++)
            #pragma unroll
            for (int q = 0; q < 4; q++) acc[i][j][q] = 0.0f;

    load_stage(sb, A, Bh, Bl, brow, bcol, 0, tid);
    CP_COMMIT();

    const int a_row0 = wm * 64 + (lane & 15);   // + mf*16
    const int b_row0 = wn * 32 + (lane & 15);   // + bq*16
    const int khalf  = lane >> 4;               // 0/1 -> k8 half

    for (int it = 0; it < NIT; it++) {
        if (it + 1 < NIT) {
            load_stage(sb + (uint32_t)((it + 1) & 1) * STAGE_BYTES,
                       A, Bh, Bl, brow, bcol, (it + 1) * GBK, tid);
            CP_COMMIT();
            cp_wait<1>();
        } else {
            cp_wait<0>();
        }
        __syncthreads();

        const uint32_t st = sb + (uint32_t)(it & 1) * STAGE_BYTES;

        #pragma unroll
        for (int ks = 0; ks < 4; ks++) {
            const int chunk = ks * 2 + khalf;     // 16B chunk index 0..7
            uint32_t Af[4][4], Bhf[4][2], Blf[4][2];
            #pragma unroll
            for (int mf = 0; mf < 4; mf++) {
                const int row = a_row0 + mf * 16;
                const uint32_t ad = st + A_OFF + (uint32_t)row * 128
                                  + (uint32_t)((chunk ^ (row & 7)) << 4);
                ldsm_x4(Af[mf], ad);
            }
            #pragma unroll
            for (int bq = 0; bq < 2; bq++) {
                const int row = b_row0 + bq * 16;
                const uint32_t off = (uint32_t)row * 128
                                   + (uint32_t)((chunk ^ (row & 7)) << 4);
                uint32_t t[4];
                ldsm_x4(t, st + BH_OFF + off);
                Bhf[bq * 2][0] = t[0];     Bhf[bq * 2][1] = t[2];
                Bhf[bq * 2 + 1][0] = t[1]; Bhf[bq * 2 + 1][1] = t[3];
                ldsm_x4(t, st + BL_OFF + off);
                Blf[bq * 2][0] = t[0];     Blf[bq * 2][1] = t[2];
                Blf[bq * 2 + 1][0] = t[1]; Blf[bq * 2 + 1][1] = t[3];
            }
            #pragma unroll
            for (int mf = 0; mf < 4; mf++)
                #pragma unroll
                for (int nf = 0; nf < 4; nf++) {
                    mma16816(acc[mf][nf], Af[mf], Bhf[nf]);
                    mma16816(acc[mf][nf], Af[mf], Blf[nf]);
                }
        }
        __syncthreads();
    }

    // epilogue: bias + optional phi
    #pragma unroll
    for (int nf = 0; nf < 4; nf++) {
        const int col = bcol + wn * 32 + nf * 8 + 2 * (lane & 3);
        const float b0 = bias[col], b1 = bias[col + 1];
        #pragma unroll
        for (int mf = 0; mf < 4; mf++) {
            const int r0 = brow + wm * 64 + mf * 16 + (lane >> 2);
            store2(C, (size_t)r0 * FF + col,
                   ep<PHI>(acc[mf][nf][0] + b0), ep<PHI>(acc[mf][nf][1] + b1));
            store2(C, (size_t)(r0 + 8) * FF + col,
                   ep<PHI>(acc[mf][nf][2] + b0), ep<PHI>(acc[mf][nf][3] + b1));
        }
    }
}

// ---------------------------------------------------------------------------
// conversions
// ---------------------------------------------------------------------------
__global__ __launch_bounds__(256)
void conv_x(const float4* __restrict__ in, __half* __restrict__ x16, int n4)
{
    for (int i = blockIdx.x * 256 + threadIdx.x; i < n4; i += gridDim.x * 256) {
        float4 v = in[i];
        union { __half h[4]; uint2 u; } H;
        H.h[0] = __float2half_rn(v.x);
        H.h[1] = __float2half_rn(v.y);
        H.h[2] = __float2half_rn(v.z);
        H.h[3] = __float2half_rn(v.w);
        *(uint2*)(x16 + 4 * (size_t)i) = H.u;
    }
}

// transpose + hi/lo split: Wt[n][k] = W[k][n]   (z selects which weight)
__global__ __launch_bounds__(256)
void conv_w4(const float* __restrict__ W0, const float* __restrict__ W1,
             const float* __restrict__ W2, const float* __restrict__ W3,
             __half* __restrict__ Th, __half* __restrict__ Tl)
{
    const float* Ws[4] = {W0, W1, W2, W3};
    const float* W = Ws[blockIdx.z];
    __half* th = Th + (size_t)blockIdx.z * FF * FF;
    __half* tl = Tl + (size_t)blockIdx.z * FF * FF;

    __shared__ float t[32][33];
    const int bx = blockIdx.x * 32, by = blockIdx.y * 32;
    const int tx = threadIdx.x, ty = threadIdx.y;
    #pragma unroll
    for (int i = ty; i < 32; i += 8)
        t[i][tx] = W[(size_t)(by + i) * FF + bx + tx];
    __syncthreads();
    #pragma unroll
    for (int i = ty; i < 32; i += 8) {
        float v = t[tx][i];   // = W[by+tx][bx+i]
        __half h = __float2half_rn(v);
        __half l = __float2half_rn(v - __half2float(h));
        size_t off = (size_t)(bx + i) * FF + by + tx;
        th[off] = h;
        tl[off] = l;
    }
}

// ---------------------------------------------------------------------------
// kv partial: per (h, b, split) compute 64x64 K^T V over SEQ_PER_SPLIT rows
// fp16 inputs, fp32 accumulation.
// ---------------------------------------------------------------------------
__global__ __launch_bounds__(256)
void kv_partial_kernel()
{
    const int h = blockIdx.x;
    const int b = blockIdx.y;
    const int s = blockIdx.z;
    const int tid = threadIdx.x;

    __shared__ float ks[32][DH];
    __shared__ float vs[32][DH];

    const int tx = tid & 15;
    const int ty = tid >> 4;

    float acc[4][4];
    #pragma unroll
    for (int i = 0; i < 4; i++)
        #pragma unroll
        for (int j = 0; j < 4; j++) acc[i][j] = 0.0f;
    float ksum_part = 0.0f;

    const size_t base = ((size_t)b * SEQ + (size_t)s * SEQ_PER_SPLIT) * FF + h * DH;
    const int lrow = tid >> 3;          // 0..31
    const int lcol = (tid & 7) * 8;     // 8 halfs per thread

    const int nchunks = SEQ_PER_SPLIT / 32;   // 4
    for (int c = 0; c < nchunks; c++) {
        const size_t cb = base + (size_t)c * 32 * FF;
        {
            uint4 rk = *(const uint4*)(g_k + cb + (size_t)lrow * FF + lcol);
            uint4 rv = *(const uint4*)(g_v + cb + (size_t)lrow * FF + lcol);
            const __half2* hk = (const __half2*)&rk;
            const __half2* hv = (const __half2*)&rv;
            #pragma unroll
            for (int j = 0; j < 4; j++) {
                float2 fk = __half22float2(hk[j]);
                float2 fv = __half22float2(hv[j]);
                ks[lrow][lcol + 2 * j]     = fk.x;
                ks[lrow][lcol + 2 * j + 1] = fk.y;
                vs[lrow][lcol + 2 * j]     = fv.x;
                vs[lrow][lcol + 2 * j + 1] = fv.y;
            }
        }
        __syncthreads();
        #pragma unroll 4
        for (int n = 0; n < 32; n++) {
            float a[4], bb[4];
            #pragma unroll
            for (int i = 0; i < 4; i++) a[i]  = ks[n][ty * 4 + i];
            #pragma unroll
            for (int j = 0; j < 4; j++) bb[j] = vs[n][tx * 4 + j];
            #pragma unroll
            for (int i = 0; i < 4; i++)
                #pragma unroll
                for (int j = 0; j < 4; j++)
                    acc[i][j] += a[i] * bb[j];
        }
        if (tid < DH) {
            float sum = 0.0f;
            #pragma unroll
            for (int n = 0; n < 32; n++) sum += ks[n][tid];
            ksum_part += sum;
        }
        __syncthreads();
    }

    const int hb = b * NH + h;
    float* kvout = g_kvp + ((size_t)s * BH + hb) * DH * DH;
    #pragma unroll
    for (int i = 0; i < 4; i++)
        #pragma unroll
        for (int j = 0; j < 4; j++)
            kvout[(ty * 4 + i) * DH + tx * 4 + j] = acc[i][j];
    if (tid < DH)
        g_ksp[((size_t)s * BH + hb) * DH + tid] = ksum_part;
}

__global__ __launch_bounds__(256)
void kv_reduce_kernel()
{
    const int idx = blockIdx.x * 256 + threadIdx.x;
    if (idx < BH * DH * DH) {
        float s = 0.0f;
        #pragma unroll
        for (int p = 0; p < KV_SPLITS; p++) s += g_kvp[(size_t)p * (BH * DH * DH) + idx];
        g_kv[idx] = s;
    }
    if (idx < BH * DH) {
        float s = 0.0f;
        #pragma unroll
        for (int p = 0; p < KV_SPLITS; p++) s += g_ksp[(size_t)p * (BH * DH) + idx];
        g_ks[idx] = s;
    }
}

// ---------------------------------------------------------------------------
// attention out: normed = (q @ kv) * 1/(q . ksum); fp16 q in, fp16 out
// ---------------------------------------------------------------------------
__global__ __launch_bounds__(256)
void attn_out_kernel()
{
    const int c = blockIdx.x;
    const int h = blockIdx.y;
    const int b = blockIdx.z;
    const int tid = threadIdx.x;
    const int hb = b * NH + h;

    __shared__ float kvs[DH * DH];
    __shared__ float kss[DH];
    __shared__ float qs[32][DH];
    __shared__ float zs[32];

    {
        const float4* kv4 = (const float4*)(g_kv + (size_t)hb * DH * DH);
        float4* s4 = (float4*)kvs;
        #pragma unroll
        for (int i = 0; i < 4; i++) s4[tid + i * 256] = kv4[tid + i * 256];
        if (tid < DH) kss[tid] = g_ks[(size_t)hb * DH + tid];
    }
    const size_t qbase = ((size_t)b * SEQ + (size_t)c * 32) * FF + h * DH;
    {
        const int lrow = tid >> 3, lcol = (tid & 7) * 8;
        uint4 rq = *(const uint4*)(g_q + qbase + (size_t)lrow * FF + lcol);
        const __half2* hq = (const __half2*)&rq;
        #pragma unroll
        for (int j = 0; j < 4; j++) {
            float2 f = __half22float2(hq[j]);
            qs[lrow][lcol + 2 * j]     = f.x;
            qs[lrow][lcol + 2 * j + 1] = f.y;
        }
    }
    __syncthreads();

    const int r  = tid >> 3;
    const int eg = tid & 7;

    if (eg == 0) {
        float s = 0.0f;
        #pragma unroll
        for (int dd = 0; dd < DH; dd++) s += qs[r][dd] * kss[dd];
        zs[r] = 1.0f / s;
    }
    __syncthreads();

    float4 oa = make_float4(0, 0, 0, 0), ob = make_float4(0, 0, 0, 0);
    const float4* kvrow = ((const float4*)kvs) + eg * 2;
    #pragma unroll
    for (int dd = 0; dd < DH; dd++) {
        float qv = qs[r][dd];
        float4 ka = kvrow[dd * 16];
        float4 kb = kvrow[dd * 16 + 1];
        oa.x += qv * ka.x; oa.y += qv * ka.y; oa.z += qv * ka.z; oa.w += qv * ka.w;
        ob.x += qv * kb.x; ob.y += qv * kb.y; ob.z += qv * kb.z; ob.w += qv * kb.w;
    }
    const float z = zs[r];
    float o[8] = { oa.x * z, oa.y * z, oa.z * z, oa.w * z,
                   ob.x * z, ob.y * z, ob.z * z, ob.w * z };

    union { __half h2[8]; uint4 u; } H;
    #pragma unroll
    for (int j = 0; j < 8; j++) H.h2[j] = __float2half_rn(o[j]);
    const size_t off = ((size_t)b * SEQ + (size_t)c * 32 + r) * FF + h * DH + eg * 8;
    *(uint4*)(g_n + off) = H.u;
}

// ---------------------------------------------------------------------------
// launch
// ---------------------------------------------------------------------------
extern "C" void kernel_launch(void* const* d_in, const int* in_sizes, int n_in,
                              void* d_out, int out_size)
{
    const float* x  = (const float*)d_in[0];
    const float* Wq = (const float*)d_in[1];
    const float* bq = (const float*)d_in[2];
    const float* Wk = (const float*)d_in[3];
    const float* bk = (const float*)d_in[4];
    const float* Wv = (const float*)d_in[5];
    const float* bv = (const float*)d_in[6];
    const float* Wo = (const float*)d_in[7];
    const float* bo = (const float*)d_in[8];
    float* out = (float*)d_out;

    __half *px, *pn, *pwh, *pwl, *pq, *pk, *pv;
    cudaGetSymbolAddress((void**)&px,  g_x);
    cudaGetSymbolAddress((void**)&pn,  g_n);
    cudaGetSymbolAddress((void**)&pwh, g_wh);
    cudaGetSymbolAddress((void**)&pwl, g_wl);
    cudaGetSymbolAddress((void**)&pq,  g_q);
    cudaGetSymbolAddress((void**)&pk,  g_k);
    cudaGetSymbolAddress((void**)&pv,  g_v);

    cudaFuncSetAttribute((const void*)mma_gemm<true,  __half>,
                         cudaFuncAttributeMaxDynamicSharedMemorySize, SMEM_DYN);
    cudaFuncSetAttribute((const void*)mma_gemm<false, __half>,
                         cudaFuncAttributeMaxDynamicSharedMemorySize, SMEM_DYN);
    cudaFuncSetAttribute((const void*)mma_gemm<false, float>,
                         cudaFuncAttributeMaxDynamicSharedMemorySize, SMEM_DYN);

    // weight transpose + split (all 4 in one launch)
    conv_w4<<<dim3(FF / 32, FF / 32, 4), dim3(32, 8)>>>(Wq, Wk, Wv, Wo, pwh, pwl);

    // x -> fp16
    conv_x<<<2048, 256>>>((const float4*)x, px, MROWS * FF / 4);

    dim3 ggrid(FF / GBN, MROWS / GBM);   // (6, 128) = 768 CTAs
    // projections (tensor cores via mma.sync), fp16 outputs
    mma_gemm<true,  __half><<<ggrid, 256, SMEM_DYN>>>(px, pwh + 0 * (size_t)FF * FF, pwl + 0 * (size_t)FF * FF, bq, pq);
    mma_gemm<true,  __half><<<ggrid, 256, SMEM_DYN>>>(px, pwh + 1 * (size_t)FF * FF, pwl + 1 * (size_t)FF * FF, bk, pk);
    mma_gemm<false, __half><<<ggrid, 256, SMEM_DYN>>>(px, pwh + 2 * (size_t)FF * FF, pwl + 2 * (size_t)FF * FF, bv, pv);

    // kv summary + reduce
    kv_partial_kernel<<<dim3(NH, BATCH, KV_SPLITS), 256>>>();
    kv_reduce_kernel<<<(BH * DH * DH + 255) / 256, 256>>>();

    // attention output (fp16 in/out)
    attn_out_kernel<<<dim3(SEQ / 32, NH, BATCH), 256>>>();

    // output projection (float out)
    mma_gemm<false, float><<<ggrid, 256, SMEM_DYN>>>(pn, pwh + 3 * (size_t)FF * FF, pwl + 3 * (size_t)FF * FF, bo, out);
}

// round 7
// speedup vs baseline: 3.9217x; 1.3651x over previous
#include <cuda_runtime.h>
#include <cuda_fp16.h>
#include <math.h>
#include <cstdint>

// ---------------------------------------------------------------------------
// Problem dims (fixed by the dataset)
// ---------------------------------------------------------------------------
#define BATCH 4
#define SEQ   4096
#define FF    768
#define NH    12
#define DH    64
#define MROWS (BATCH*SEQ)     // 16384
#define BH    (BATCH*NH)      // 48
#define KV_SPLITS 32
#define SEQ_PER_SPLIT (SEQ/KV_SPLITS)   // 128

// ---------------------------------------------------------------------------
// Static device scratch (no runtime allocation allowed)
// ---------------------------------------------------------------------------
__device__ __half  g_x [MROWS * FF];        // x in fp16
__device__ __half  g_q [MROWS * FF];        // q = phi(xWq+b) fp16
__device__ __half  g_k [MROWS * FF];        // k fp16
__device__ __half  g_v [MROWS * FF];        // v fp16
__device__ __half  g_n [MROWS * FF];        // attn output fp16
__device__ __half  g_w [4][FF * FF];        // transposed weights fp16 [n][k]
__device__ float g_kvp[KV_SPLITS * BH * DH * DH];
__device__ float g_ksp[KV_SPLITS * BH * DH];
__device__ float g_kv [BH * DH * DH];
__device__ float g_ks [BH * DH];

// ---------------------------------------------------------------------------
// PTX helpers (baseline sm_80-class instructions only)
// ---------------------------------------------------------------------------
__device__ __forceinline__ uint32_t smem_u32(const void* p) {
    uint32_t a;
    asm("{ .reg .u64 t; cvta.to.shared.u64 t, %1; cvt.u32.u64 %0, t; }"
        : "=r"(a) : "l"(p));
    return a;
}

__device__ __forceinline__ void cp16(uint32_t dst, const void* src) {
    asm volatile("cp.async.cg.shared.global [%0], [%1], 16;" :: "r"(dst), "l"(src));
}
#define CP_COMMIT() asm volatile("cp.async.commit_group;" ::: "memory")
template <int N>
__device__ __forceinline__ void cp_wait() {
    asm volatile("cp.async.wait_group %0;" :: "n"(N) : "memory");
}

__device__ __forceinline__ void ldsm_x4(uint32_t* r, uint32_t addr) {
    asm volatile("ldmatrix.sync.aligned.m8n8.x4.shared.b16 {%0,%1,%2,%3}, [%4];"
                 : "=r"(r[0]), "=r"(r[1]), "=r"(r[2]), "=r"(r[3]) : "r"(addr));
}

// D += A * B   (m16n8k16, fp16 in, fp32 accum)
__device__ __forceinline__ void mma16816(float* d, const uint32_t* a, const uint32_t* b) {
    asm volatile(
        "mma.sync.aligned.m16n8k16.row.col.f32.f16.f16.f32 "
        "{%0,%1,%2,%3}, {%4,%5,%6,%7}, {%8,%9}, {%0,%1,%2,%3};"
        : "+f"(d[0]), "+f"(d[1]), "+f"(d[2]), "+f"(d[3])
        : "r"(a[0]), "r"(a[1]), "r"(a[2]), "r"(a[3]), "r"(b[0]), "r"(b[1]));
}

// ---------------------------------------------------------------------------
// mma_gemm: C[16384,768] = A[M,K] @ W[N,K]^T + bias   (pure fp16 operands)
// CTA tile 128x128, BK=64, 256 threads = 8 warps (2 M x 4 N), warp 64x32.
// 128B smem rows + XOR-8 chunk swizzle -> conflict-free ldmatrix & stores.
// 2-stage cp.async double buffer (32KB/stage); 2 CTAs/SM.
// ---------------------------------------------------------------------------
#define GBM 128
#define GBN 128
#define GBK 64
#define A_OFF  0
#define A_BYTES  (128 * 128)        // 16 KB
#define B_OFF  A_BYTES
#define B_BYTES  (128 * 128)        // 16 KB
#define STAGE_BYTES (A_BYTES + B_BYTES)   // 32 KB
#define SMEM_DYN (2 * STAGE_BYTES)        // 64 KB
#define NIT (FF / GBK)              // 12

template <bool PHI>
__device__ __forceinline__ float ep(float v) {
    if (PHI) return v > 0.0f ? v + 1.0f : expf(v);   // elu(v)+1
    return v;
}

__device__ __forceinline__ void store2(float* C, size_t idx, float a, float b) {
    *(float2*)(C + idx) = make_float2(a, b);
}
__device__ __forceinline__ void store2(__half* C, size_t idx, float a, float b) {
    *(__half2*)(C + idx) = __floats2half2_rn(a, b);
}

// 256 threads fill one 32KB stage: 4 chunks/thread per matrix (A, B).
__device__ __forceinline__ void load_stage(uint32_t st,
        const __half* __restrict__ A, const __half* __restrict__ B,
        int brow, int bcol, int kbase, int tid)
{
    #pragma unroll
    for (int i = 0; i < 4; i++) {
        const int cid = tid + i * 256;        // 0..1023
        const int r = cid >> 3, c = cid & 7;
        const uint32_t sw = (uint32_t)r * 128 + (uint32_t)((c ^ (r & 7)) << 4);
        cp16(st + A_OFF + sw, A + (size_t)(brow + r) * FF + kbase + c * 8);
        cp16(st + B_OFF + sw, B + (size_t)(bcol + r) * FF + kbase + c * 8);
    }
}

template <bool PHI, typename OutT>
__global__ __launch_bounds__(256, 2)
void mma_gemm(const __half* __restrict__ A, const __half* __restrict__ B,
              const float* __restrict__ bias, OutT* __restrict__ C)
{
    extern __shared__ char dsm[];
    const uint32_t sb = smem_u32(dsm);

    const int tid  = threadIdx.x;
    const int warp = tid >> 5;
    const int lane = tid & 31;
    const int wm   = warp & 1;        // 0..1 -> M offset 64*wm
    const int wn   = warp >> 1;       // 0..3 -> N offset 32*wn
    const int brow = blockIdx.y * GBM;
    const int bcol = blockIdx.x * GBN;

    float acc[4][4][4];
    #pragma unroll
    for (int i = 0; i < 4; i++)
        #pragma unroll
        for (int j = 0; j < 4; j++)
            #pragma unroll
            for (int q = 0; q < 4; q++) acc[i][j][q] = 0.0f;

    load_stage(sb, A, B, brow, bcol, 0, tid);
    CP_COMMIT();

    // XOR-folded swizzled base addresses: rowbase bits<7 are zero, so
    // addr(chunk) = (rowbase | ((row&7)<<4)) ^ (chunk<<4).
    const int a_row0 = wm * 64 + (lane & 15);
    const int b_row0 = wn * 32 + (lane & 15);
    uint32_t a_base[4], b_base[2];
    #pragma unroll
    for (int mf = 0; mf < 4; mf++) {
        const int row = a_row0 + mf * 16;
        a_base[mf] = A_OFF + (uint32_t)row * 128 + (uint32_t)((row & 7) << 4);
    }
    #pragma unroll
    for (int bq = 0; bq < 2; bq++) {
        const int row = b_row0 + bq * 16;
        b_base[bq] = B_OFF + (uint32_t)row * 128 + (uint32_t)((row & 7) << 4);
    }
    const uint32_t khx = (uint32_t)(lane >> 4) << 4;   // khalf XOR bits

    for (int it = 0; it < NIT; it++) {
        if (it + 1 < NIT) {
            load_stage(sb + (uint32_t)((it + 1) & 1) * STAGE_BYTES,
                       A, B, brow, bcol, (it + 1) * GBK, tid);
            CP_COMMIT();
            cp_wait<1>();
        } else {
            cp_wait<0>();
        }
        __syncthreads();

        const uint32_t st = sb + (uint32_t)(it & 1) * STAGE_BYTES;

        #pragma unroll
        for (int ks = 0; ks < 4; ks++) {
            const uint32_t cx = ((uint32_t)(ks * 2) << 4) ^ khx;  // chunk<<4
            uint32_t Af[4][4], Bf[4][2];
            #pragma unroll
            for (int mf = 0; mf < 4; mf++)
                ldsm_x4(Af[mf], st + (a_base[mf] ^ cx));
            #pragma unroll
            for (int bq = 0; bq < 2; bq++) {
                uint32_t t[4];
                ldsm_x4(t, st + (b_base[bq] ^ cx));
                Bf[bq * 2][0] = t[0];     Bf[bq * 2][1] = t[2];
                Bf[bq * 2 + 1][0] = t[1]; Bf[bq * 2 + 1][1] = t[3];
            }
            #pragma unroll
            for (int mf = 0; mf < 4; mf++)
                #pragma unroll
                for (int nf = 0; nf < 4; nf++)
                    mma16816(acc[mf][nf], Af[mf], Bf[nf]);
        }
        __syncthreads();
    }

    // epilogue: bias + optional phi
    #pragma unroll
    for (int nf = 0; nf < 4; nf++) {
        const int col = bcol + wn * 32 + nf * 8 + 2 * (lane & 3);
        const float b0 = bias[col], b1 = bias[col + 1];
        #pragma unroll
        for (int mf = 0; mf < 4; mf++) {
            const int r0 = brow + wm * 64 + mf * 16 + (lane >> 2);
            store2(C, (size_t)r0 * FF + col,
                   ep<PHI>(acc[mf][nf][0] + b0), ep<PHI>(acc[mf][nf][1] + b1));
            store2(C, (size_t)(r0 + 8) * FF + col,
                   ep<PHI>(acc[mf][nf][2] + b0), ep<PHI>(acc[mf][nf][3] + b1));
        }
    }
}

// ---------------------------------------------------------------------------
// conversions
// ---------------------------------------------------------------------------
__global__ __launch_bounds__(256)
void conv_x(const float4* __restrict__ in, __half* __restrict__ x16, int n4)
{
    for (int i = blockIdx.x * 256 + threadIdx.x; i < n4; i += gridDim.x * 256) {
        float4 v = in[i];
        union { __half h[4]; uint2 u; } H;
        H.h[0] = __float2half_rn(v.x);
        H.h[1] = __float2half_rn(v.y);
        H.h[2] = __float2half_rn(v.z);
        H.h[3] = __float2half_rn(v.w);
        *(uint2*)(x16 + 4 * (size_t)i) = H.u;
    }
}

// transpose: Wt[n][k] = W[k][n] in fp16   (z selects which weight)
__global__ __launch_bounds__(256)
void conv_w4(const float* __restrict__ W0, const float* __restrict__ W1,
             const float* __restrict__ W2, const float* __restrict__ W3,
             __half* __restrict__ T)
{
    const float* Ws[4] = {W0, W1, W2, W3};
    const float* W = Ws[blockIdx.z];
    __half* th = T + (size_t)blockIdx.z * FF * FF;

    __shared__ float t[32][33];
    const int bx = blockIdx.x * 32, by = blockIdx.y * 32;
    const int tx = threadIdx.x, ty = threadIdx.y;
    #pragma unroll
    for (int i = ty; i < 32; i += 8)
        t[i][tx] = W[(size_t)(by + i) * FF + bx + tx];
    __syncthreads();
    #pragma unroll
    for (int i = ty; i < 32; i += 8)
        th[(size_t)(bx + i) * FF + by + tx] = __float2half_rn(t[tx][i]);
}

// ---------------------------------------------------------------------------
// kv partial: per (h, b, split) compute 64x64 K^T V over SEQ_PER_SPLIT rows
// fp16 inputs, fp32 accumulation.
// ---------------------------------------------------------------------------
__global__ __launch_bounds__(256)
void kv_partial_kernel()
{
    const int h = blockIdx.x;
    const int b = blockIdx.y;
    const int s = blockIdx.z;
    const int tid = threadIdx.x;

    __shared__ float ks[32][DH];
    __shared__ float vs[32][DH];

    const int tx = tid & 15;
    const int ty = tid >> 4;

    float acc[4][4];
    #pragma unroll
    for (int i = 0; i < 4; i++)
        #pragma unroll
        for (int j = 0; j < 4; j++) acc[i][j] = 0.0f;
    float ksum_part = 0.0f;

    const size_t base = ((size_t)b * SEQ + (size_t)s * SEQ_PER_SPLIT) * FF + h * DH;
    const int lrow = tid >> 3;          // 0..31
    const int lcol = (tid & 7) * 8;     // 8 halfs per thread

    const int nchunks = SEQ_PER_SPLIT / 32;   // 4
    for (int c = 0; c < nchunks; c++) {
        const size_t cb = base + (size_t)c * 32 * FF;
        {
            uint4 rk = *(const uint4*)(g_k + cb + (size_t)lrow * FF + lcol);
            uint4 rv = *(const uint4*)(g_v + cb + (size_t)lrow * FF + lcol);
            const __half2* hk = (const __half2*)&rk;
            const __half2* hv = (const __half2*)&rv;
            #pragma unroll
            for (int j = 0; j < 4; j++) {
                float2 fk = __half22float2(hk[j]);
                float2 fv = __half22float2(hv[j]);
                ks[lrow][lcol + 2 * j]     = fk.x;
                ks[lrow][lcol + 2 * j + 1] = fk.y;
                vs[lrow][lcol + 2 * j]     = fv.x;
                vs[lrow][lcol + 2 * j + 1] = fv.y;
            }
        }
        __syncthreads();
        #pragma unroll 4
        for (int n = 0; n < 32; n++) {
            float a[4], bb[4];
            #pragma unroll
            for (int i = 0; i < 4; i++) a[i]  = ks[n][ty * 4 + i];
            #pragma unroll
            for (int j = 0; j < 4; j++) bb[j] = vs[n][tx * 4 + j];
            #pragma unroll
            for (int i = 0; i < 4; i++)
                #pragma unroll
                for (int j = 0; j < 4; j++)
                    acc[i][j] += a[i] * bb[j];
        }
        if (tid < DH) {
            float sum = 0.0f;
            #pragma unroll
            for (int n = 0; n < 32; n++) sum += ks[n][tid];
            ksum_part += sum;
        }
        __syncthreads();
    }

    const int hb = b * NH + h;
    float* kvout = g_kvp + ((size_t)s * BH + hb) * DH * DH;
    #pragma unroll
    for (int i = 0; i < 4; i++)
        #pragma unroll
        for (int j = 0; j < 4; j++)
            kvout[(ty * 4 + i) * DH + tx * 4 + j] = acc[i][j];
    if (tid < DH)
        g_ksp[((size_t)s * BH + hb) * DH + tid] = ksum_part;
}

__global__ __launch_bounds__(256)
void kv_reduce_kernel()
{
    const int idx = blockIdx.x * 256 + threadIdx.x;
    if (idx < BH * DH * DH) {
        float s = 0.0f;
        #pragma unroll
        for (int p = 0; p < KV_SPLITS; p++) s += g_kvp[(size_t)p * (BH * DH * DH) + idx];
        g_kv[idx] = s;
    }
    if (idx < BH * DH) {
        float s = 0.0f;
        #pragma unroll
        for (int p = 0; p < KV_SPLITS; p++) s += g_ksp[(size_t)p * (BH * DH) + idx];
        g_ks[idx] = s;
    }
}

// ---------------------------------------------------------------------------
// attention out: normed = (q @ kv) * 1/(q . ksum); fp16 q in, fp16 out
// ---------------------------------------------------------------------------
__global__ __launch_bounds__(256)
void attn_out_kernel()
{
    const int c = blockIdx.x;
    const int h = blockIdx.y;
    const int b = blockIdx.z;
    const int tid = threadIdx.x;
    const int hb = b * NH + h;

    __shared__ float kvs[DH * DH];
    __shared__ float kss[DH];
    __shared__ float qs[32][DH];
    __shared__ float zs[32];

    {
        const float4* kv4 = (const float4*)(g_kv + (size_t)hb * DH * DH);
        float4* s4 = (float4*)kvs;
        #pragma unroll
        for (int i = 0; i < 4; i++) s4[tid + i * 256] = kv4[tid + i * 256];
        if (tid < DH) kss[tid] = g_ks[(size_t)hb * DH + tid];
    }
    const size_t qbase = ((size_t)b * SEQ + (size_t)c * 32) * FF + h * DH;
    {
        const int lrow = tid >> 3, lcol = (tid & 7) * 8;
        uint4 rq = *(const uint4*)(g_q + qbase + (size_t)lrow * FF + lcol);
        const __half2* hq = (const __half2*)&rq;
        #pragma unroll
        for (int j = 0; j < 4; j++) {
            float2 f = __half22float2(hq[j]);
            qs[lrow][lcol + 2 * j]     = f.x;
            qs[lrow][lcol + 2 * j + 1] = f.y;
        }
    }
    __syncthreads();

    const int r  = tid >> 3;
    const int eg = tid & 7;

    if (eg == 0) {
        float s = 0.0f;
        #pragma unroll
        for (int dd = 0; dd < DH; dd++) s += qs[r][dd] * kss[dd];
        zs[r] = 1.0f / s;
    }
    __syncthreads();

    float4 oa = make_float4(0, 0, 0, 0), ob = make_float4(0, 0, 0, 0);
    const float4* kvrow = ((const float4*)kvs) + eg * 2;
    #pragma unroll
    for (int dd = 0; dd < DH; dd++) {
        float qv = qs[r][dd];
        float4 ka = kvrow[dd * 16];
        float4 kb = kvrow[dd * 16 + 1];
        oa.x += qv * ka.x; oa.y += qv * ka.y; oa.z += qv * ka.z; oa.w += qv * ka.w;
        ob.x += qv * kb.x; ob.y += qv * kb.y; ob.z += qv * kb.z; ob.w += qv * kb.w;
    }
    const float z = zs[r];
    float o[8] = { oa.x * z, oa.y * z, oa.z * z, oa.w * z,
                   ob.x * z, ob.y * z, ob.z * z, ob.w * z };

    union { __half h2[8]; uint4 u; } H;
    #pragma unroll
    for (int j = 0; j < 8; j++) H.h2[j] = __float2half_rn(o[j]);
    const size_t off = ((size_t)b * SEQ + (size_t)c * 32 + r) * FF + h * DH + eg * 8;
    *(uint4*)(g_n + off) = H.u;
}

// ---------------------------------------------------------------------------
// launch
// ---------------------------------------------------------------------------
extern "C" void kernel_launch(void* const* d_in, const int* in_sizes, int n_in,
                              void* d_out, int out_size)
{
    const float* x  = (const float*)d_in[0];
    const float* Wq = (const float*)d_in[1];
    const float* bq = (const float*)d_in[2];
    const float* Wk = (const float*)d_in[3];
    const float* bk = (const float*)d_in[4];
    const float* Wv = (const float*)d_in[5];
    const float* bv = (const float*)d_in[6];
    const float* Wo = (const float*)d_in[7];
    const float* bo = (const float*)d_in[8];
    float* out = (float*)d_out;

    __half *px, *pn, *pw, *pq, *pk, *pv;
    cudaGetSymbolAddress((void**)&px, g_x);
    cudaGetSymbolAddress((void**)&pn, g_n);
    cudaGetSymbolAddress((void**)&pw, g_w);
    cudaGetSymbolAddress((void**)&pq, g_q);
    cudaGetSymbolAddress((void**)&pk, g_k);
    cudaGetSymbolAddress((void**)&pv, g_v);

    cudaFuncSetAttribute((const void*)mma_gemm<true,  __half>,
                         cudaFuncAttributeMaxDynamicSharedMemorySize, SMEM_DYN);
    cudaFuncSetAttribute((const void*)mma_gemm<false, __half>,
                         cudaFuncAttributeMaxDynamicSharedMemorySize, SMEM_DYN);
    cudaFuncSetAttribute((const void*)mma_gemm<false, float>,
                         cudaFuncAttributeMaxDynamicSharedMemorySize, SMEM_DYN);

    // weight transpose -> fp16 (all 4 in one launch)
    conv_w4<<<dim3(FF / 32, FF / 32, 4), dim3(32, 8)>>>(Wq, Wk, Wv, Wo, pw);

    // x -> fp16
    conv_x<<<2048, 256>>>((const float4*)x, px, MROWS * FF / 4);

    dim3 ggrid(FF / GBN, MROWS / GBM);   // (6, 128) = 768 CTAs
    // projections (pure fp16 tensor-core GEMMs)
    mma_gemm<true,  __half><<<ggrid, 256, SMEM_DYN>>>(px, pw + 0 * (size_t)FF * FF, bq, pq);
    mma_gemm<true,  __half><<<ggrid, 256, SMEM_DYN>>>(px, pw + 1 * (size_t)FF * FF, bk, pk);
    mma_gemm<false, __half><<<ggrid, 256, SMEM_DYN>>>(px, pw + 2 * (size_t)FF * FF, bv, pv);

    // kv summary + reduce
    kv_partial_kernel<<<dim3(NH, BATCH, KV_SPLITS), 256>>>();
    kv_reduce_kernel<<<(BH * DH * DH + 255) / 256, 256>>>();

    // attention output (fp16 in/out)
    attn_out_kernel<<<dim3(SEQ / 32, NH, BATCH), 256>>>();

    // output projection (float out)
    mma_gemm<false, float><<<ggrid, 256, SMEM_DYN>>>(pn, pw + 3 * (size_t)FF * FF, bo, out);
}

// round 8
// speedup vs baseline: 6.4777x; 1.6517x over previous
#include <cuda_runtime.h>
#include <cuda_fp16.h>
#include <math.h>
#include <cstdint>

// ---------------------------------------------------------------------------
// Problem dims (fixed by the dataset)
// ---------------------------------------------------------------------------
#define BATCH 4
#define SEQ   4096
#define FF    768
#define NH    12
#define DH    64
#define MROWS (BATCH*SEQ)     // 16384
#define BH    (BATCH*NH)      // 48
#define NSPLIT 16
#define NPS (SEQ / NSPLIT)    // 256 sequence rows per split

// ---------------------------------------------------------------------------
// Static device scratch (no runtime allocation allowed)
// ---------------------------------------------------------------------------
__device__ __half  g_x [MROWS * FF];        // x fp16
__device__ __half  g_q [MROWS * FF];        // q = phi(xWq+b) fp16
__device__ __half  g_k [MROWS * FF];        // k fp16
__device__ __half  g_v [MROWS * FF];        // v fp16
__device__ __half  g_n [MROWS * FF];        // attn output fp16
__device__ __half  g_w [4][FF * FF];        // transposed weights fp16 [n][k]
__device__ float  g_kvp[NSPLIT * BH * DH * DH];   // partial KV^T (e,d) fp32
__device__ float  g_ksp[NSPLIT * BH * DH];        // partial ksum fp32
__device__ __half g_kvT[BH * DH * DH];            // KV^T fp16 [bh][e][d]
__device__ float  g_ks [BH * DH];                 // ksum fp32

// ---------------------------------------------------------------------------
// PTX helpers (baseline sm_80-class instructions only)
// ---------------------------------------------------------------------------
__device__ __forceinline__ uint32_t smem_u32(const void* p) {
    uint32_t a;
    asm("{ .reg .u64 t; cvta.to.shared.u64 t, %1; cvt.u32.u64 %0, t; }"
        : "=r"(a) : "l"(p));
    return a;
}

__device__ __forceinline__ void cp16(uint32_t dst, const void* src) {
    asm volatile("cp.async.cg.shared.global [%0], [%1], 16;" :: "r"(dst), "l"(src));
}
#define CP_COMMIT() asm volatile("cp.async.commit_group;" ::: "memory")
template <int N>
__device__ __forceinline__ void cp_wait() {
    asm volatile("cp.async.wait_group %0;" :: "n"(N) : "memory");
}

__device__ __forceinline__ void ldsm_x4(uint32_t* r, uint32_t addr) {
    asm volatile("ldmatrix.sync.aligned.m8n8.x4.shared.b16 {%0,%1,%2,%3}, [%4];"
                 : "=r"(r[0]), "=r"(r[1]), "=r"(r[2]), "=r"(r[3]) : "r"(addr));
}
__device__ __forceinline__ void ldsm_x4_t(uint32_t* r, uint32_t addr) {
    asm volatile("ldmatrix.sync.aligned.m8n8.x4.trans.shared.b16 {%0,%1,%2,%3}, [%4];"
                 : "=r"(r[0]), "=r"(r[1]), "=r"(r[2]), "=r"(r[3]) : "r"(addr));
}

// D += A * B   (m16n8k16, fp16 in, fp32 accum)
__device__ __forceinline__ void mma16816(float* d, const uint32_t* a, const uint32_t* b) {
    asm volatile(
        "mma.sync.aligned.m16n8k16.row.col.f32.f16.f16.f32 "
        "{%0,%1,%2,%3}, {%4,%5,%6,%7}, {%8,%9}, {%0,%1,%2,%3};"
        : "+f"(d[0]), "+f"(d[1]), "+f"(d[2]), "+f"(d[3])
        : "r"(a[0]), "r"(a[1]), "r"(a[2]), "r"(a[3]), "r"(b[0]), "r"(b[1]));
}

// ---------------------------------------------------------------------------
// mma_gemm: C[16384,768] = A[M,K] @ W[N,K]^T + bias   (pure fp16 operands)
// ---------------------------------------------------------------------------
#define GBM 128
#define GBN 128
#define GBK 64
#define A_OFF  0
#define A_BYTES  (128 * 128)
#define B_OFF  A_BYTES
#define B_BYTES  (128 * 128)
#define STAGE_BYTES (A_BYTES + B_BYTES)   // 32 KB
#define SMEM_DYN (2 * STAGE_BYTES)        // 64 KB
#define NIT (FF / GBK)              // 12

template <bool PHI>
__device__ __forceinline__ float ep(float v) {
    if (PHI) return v > 0.0f ? v + 1.0f : expf(v);   // elu(v)+1
    return v;
}

__device__ __forceinline__ void store2(float* C, size_t idx, float a, float b) {
    *(float2*)(C + idx) = make_float2(a, b);
}
__device__ __forceinline__ void store2(__half* C, size_t idx, float a, float b) {
    *(__half2*)(C + idx) = __floats2half2_rn(a, b);
}

__device__ __forceinline__ void load_stage(uint32_t st,
        const __half* __restrict__ A, const __half* __restrict__ B,
        int brow, int bcol, int kbase, int tid)
{
    #pragma unroll
    for (int i = 0; i < 4; i++) {
        const int cid = tid + i * 256;
        const int r = cid >> 3, c = cid & 7;
        const uint32_t sw = (uint32_t)r * 128 + (uint32_t)((c ^ (r & 7)) << 4);
        cp16(st + A_OFF + sw, A + (size_t)(brow + r) * FF + kbase + c * 8);
        cp16(st + B_OFF + sw, B + (size_t)(bcol + r) * FF + kbase + c * 8);
    }
}

template <bool PHI, typename OutT>
__global__ __launch_bounds__(256, 2)
void mma_gemm(const __half* __restrict__ A, const __half* __restrict__ B,
              const float* __restrict__ bias, OutT* __restrict__ C)
{
    extern __shared__ char dsm[];
    const uint32_t sb = smem_u32(dsm);

    const int tid  = threadIdx.x;
    const int warp = tid >> 5;
    const int lane = tid & 31;
    const int wm   = warp & 1;
    const int wn   = warp >> 1;
    const int brow = blockIdx.y * GBM;
    const int bcol = blockIdx.x * GBN;

    float acc[4][4][4];
    #pragma unroll
    for (int i = 0; i < 4; i++)
        #pragma unroll
        for (int j = 0; j < 4; j++)
            #pragma unroll
            for (int q = 0; q < 4; q++) acc[i][j][q] = 0.0f;

    load_stage(sb, A, B, brow, bcol, 0, tid);
    CP_COMMIT();

    const int a_row0 = wm * 64 + (lane & 15);
    const int b_row0 = wn * 32 + (lane & 15);
    uint32_t a_base[4], b_base[2];
    #pragma unroll
    for (int mf = 0; mf < 4; mf++) {
        const int row = a_row0 + mf * 16;
        a_base[mf] = A_OFF + (uint32_t)row * 128 + (uint32_t)((row & 7) << 4);
    }
    #pragma unroll
    for (int bq = 0; bq < 2; bq++) {
        const int row = b_row0 + bq * 16;
        b_base[bq] = B_OFF + (uint32_t)row * 128 + (uint32_t)((row & 7) << 4);
    }
    const uint32_t khx = (uint32_t)(lane >> 4) << 4;

    for (int it = 0; it < NIT; it++) {
        if (it + 1 < NIT) {
            load_stage(sb + (uint32_t)((it + 1) & 1) * STAGE_BYTES,
                       A, B, brow, bcol, (it + 1) * GBK, tid);
            CP_COMMIT();
            cp_wait<1>();
        } else {
            cp_wait<0>();
        }
        __syncthreads();

        const uint32_t st = sb + (uint32_t)(it & 1) * STAGE_BYTES;

        #pragma unroll
        for (int ks = 0; ks < 4; ks++) {
            const uint32_t cx = ((uint32_t)(ks * 2) << 4) ^ khx;
            uint32_t Af[4][4], Bf[4][2];
            #pragma unroll
            for (int mf = 0; mf < 4; mf++)
                ldsm_x4(Af[mf], st + (a_base[mf] ^ cx));
            #pragma unroll
            for (int bq = 0; bq < 2; bq++) {
                uint32_t t[4];
                ldsm_x4(t, st + (b_base[bq] ^ cx));
                Bf[bq * 2][0] = t[0];     Bf[bq * 2][1] = t[2];
                Bf[bq * 2 + 1][0] = t[1]; Bf[bq * 2 + 1][1] = t[3];
            }
            #pragma unroll
            for (int mf = 0; mf < 4; mf++)
                #pragma unroll
                for (int nf = 0; nf < 4; nf++)
                    mma16816(acc[mf][nf], Af[mf], Bf[nf]);
        }
        __syncthreads();
    }

    #pragma unroll
    for (int nf = 0; nf < 4; nf++) {
        const int col = bcol + wn * 32 + nf * 8 + 2 * (lane & 3);
        const float b0 = bias[col], b1 = bias[col + 1];
        #pragma unroll
        for (int mf = 0; mf < 4; mf++) {
            const int r0 = brow + wm * 64 + mf * 16 + (lane >> 2);
            store2(C, (size_t)r0 * FF + col,
                   ep<PHI>(acc[mf][nf][0] + b0), ep<PHI>(acc[mf][nf][1] + b1));
            store2(C, (size_t)(r0 + 8) * FF + col,
                   ep<PHI>(acc[mf][nf][2] + b0), ep<PHI>(acc[mf][nf][3] + b1));
        }
    }
}

// ---------------------------------------------------------------------------
// conversions
// ---------------------------------------------------------------------------
__global__ __launch_bounds__(256)
void conv_x(const float4* __restrict__ in, __half* __restrict__ x16, int n4)
{
    for (int i = blockIdx.x * 256 + threadIdx.x; i < n4; i += gridDim.x * 256) {
        float4 v = in[i];
        union { __half h[4]; uint2 u; } H;
        H.h[0] = __float2half_rn(v.x);
        H.h[1] = __float2half_rn(v.y);
        H.h[2] = __float2half_rn(v.z);
        H.h[3] = __float2half_rn(v.w);
        *(uint2*)(x16 + 4 * (size_t)i) = H.u;
    }
}

__global__ __launch_bounds__(256)
void conv_w4(const float* __restrict__ W0, const float* __restrict__ W1,
             const float* __restrict__ W2, const float* __restrict__ W3,
             __half* __restrict__ T)
{
    const float* Ws[4] = {W0, W1, W2, W3};
    const float* W = Ws[blockIdx.z];
    __half* th = T + (size_t)blockIdx.z * FF * FF;

    __shared__ float t[32][33];
    const int bx = blockIdx.x * 32, by = blockIdx.y * 32;
    const int tx = threadIdx.x, ty = threadIdx.y;
    #pragma unroll
    for (int i = ty; i < 32; i += 8)
        t[i][tx] = W[(size_t)(by + i) * FF + bx + tx];
    __syncthreads();
    #pragma unroll
    for (int i = ty; i < 32; i += 8)
        th[(size_t)(bx + i) * FF + by + tx] = __float2half_rn(t[tx][i]);
}

// ---------------------------------------------------------------------------
// kv_partial_mma: per (bh, split) KV^T[e][d] = sum_n v[n][e] k[n][d]  (tensor cores)
// 128 threads = 4 warps, warp w -> e rows 16w..16w+15.
// k,v tiles loaded [32 n][64 dim] fp16 swizzled; ldmatrix.trans fragments.
// ksum via extra all-ones-A MMA on warp 0.
// ---------------------------------------------------------------------------
__global__ __launch_bounds__(128)
void kv_partial_mma()
{
    const int bh = blockIdx.x;            // b*NH + h
    const int sp = blockIdx.y;
    const int b  = bh / NH;
    const int h  = bh % NH;
    const int tid  = threadIdx.x;
    const int warp = tid >> 5;
    const int lane = tid & 31;

    __shared__ __align__(16) char kt[32 * 128];   // k tile 32x64 fp16
    __shared__ __align__(16) char vt[32 * 128];   // v tile 32x64 fp16
    const uint32_t kts = smem_u32(kt);
    const uint32_t vts = smem_u32(vt);

    float acc[8][4];
    #pragma unroll
    for (int i = 0; i < 8; i++)
        #pragma unroll
        for (int q = 0; q < 4; q++) acc[i][q] = 0.0f;
    float ksa[8][4];
    #pragma unroll
    for (int i = 0; i < 8; i++)
        #pragma unroll
        for (int q = 0; q < 4; q++) ksa[i][q] = 0.0f;

    const size_t gbase = ((size_t)b * SEQ + (size_t)sp * NPS) * FF + h * DH;

    // trans-ldmatrix lane addressing: row = (lane&15), colchunk = base + (lane>>4)
    const int lrow = lane & 15;
    const int lhi  = lane >> 4;

    uint32_t ones[4];
    #pragma unroll
    for (int i = 0; i < 4; i++) ones[i] = 0x3C003C00u;  // fp16 1.0 x2

    for (int c = 0; c < NPS / 32; c++) {        // 8 chunks of 32 n
        // load 32x64 k and v tiles (2 cp16 per tile per thread)
        #pragma unroll
        for (int i = 0; i < 2; i++) {
            const int cid = tid + i * 128;      // 0..255
            const int r = cid >> 3, ch = cid & 7;
            const uint32_t sw = (uint32_t)r * 128 + (uint32_t)((ch ^ (r & 7)) << 4);
            const size_t go = gbase + (size_t)(c * 32 + r) * FF + ch * 8;
            cp16(kts + sw, g_k + go);
            cp16(vts + sw, g_v + go);
        }
        CP_COMMIT();
        cp_wait<0>();
        __syncthreads();

        #pragma unroll
        for (int ks2 = 0; ks2 < 2; ks2++) {     // two 16-n MMA steps
            const int nb = ks2 * 16;
            // A = v^T fragment: warp's 16 e-rows = cols 16w..16w+15 of v tile
            uint32_t t[4], Afr[4];
            {
                const int row = nb + lrow;
                const int ch  = 2 * warp + lhi;
                ldsm_x4_t(t, vts + (uint32_t)row * 128
                             + (uint32_t)((ch ^ (row & 7)) << 4));
                Afr[0] = t[0]; Afr[1] = t[2]; Afr[2] = t[1]; Afr[3] = t[3];
            }
            // B = k^T fragments: 8 d-groups via 4 trans x4 loads
            uint32_t Bf[8][2];
            #pragma unroll
            for (int j = 0; j < 4; j++) {
                const int row = nb + lrow;
                const int ch  = 2 * j + lhi;
                uint32_t u[4];
                ldsm_x4_t(u, kts + (uint32_t)row * 128
                             + (uint32_t)((ch ^ (row & 7)) << 4));
                Bf[2 * j][0] = u[0];     Bf[2 * j][1] = u[1];
                Bf[2 * j + 1][0] = u[2]; Bf[2 * j + 1][1] = u[3];
            }
            #pragma unroll
            for (int dg = 0; dg < 8; dg++)
                mma16816(acc[dg], Afr, Bf[dg]);
            if (warp == 0) {
                #pragma unroll
                for (int dg = 0; dg < 8; dg++)
                    mma16816(ksa[dg], ones, Bf[dg]);
            }
        }
        __syncthreads();
    }

    // write partials: KV^T rows e = 16*warp + g (+8), cols d = 8*dg + 2t
    const int g = lane >> 2, tq = lane & 3;
    float* kvout = g_kvp + ((size_t)sp * BH + bh) * DH * DH;
    #pragma unroll
    for (int dg = 0; dg < 8; dg++) {
        const int e0 = 16 * warp + g;
        const int d0 = 8 * dg + 2 * tq;
        store2(kvout, (size_t)e0 * DH + d0,       acc[dg][0], acc[dg][1]);
        store2(kvout, (size_t)(e0 + 8) * DH + d0, acc[dg][2], acc[dg][3]);
    }
    if (warp == 0 && g == 0) {   // lanes 0-3 hold row 0 of the ones-MMA = ksum
        float* ksout = g_ksp + ((size_t)sp * BH + bh) * DH;
        #pragma unroll
        for (int dg = 0; dg < 8; dg++) {
            ksout[8 * dg + 2 * tq]     = ksa[dg][0];
            ksout[8 * dg + 2 * tq + 1] = ksa[dg][1];
        }
    }
}

// ---------------------------------------------------------------------------
// kv_reduce: sum split partials -> fp16 KV^T + fp32 ksum
// ---------------------------------------------------------------------------
__global__ __launch_bounds__(256)
void kv_reduce_kernel()
{
    const int idx = blockIdx.x * 256 + threadIdx.x;
    if (idx < BH * DH * DH) {
        float s = 0.0f;
        #pragma unroll
        for (int p = 0; p < NSPLIT; p++) s += g_kvp[(size_t)p * (BH * DH * DH) + idx];
        g_kvT[idx] = __float2half_rn(s);
    }
    if (idx < BH * DH) {
        float s = 0.0f;
        #pragma unroll
        for (int p = 0; p < NSPLIT; p++) s += g_ksp[(size_t)p * (BH * DH) + idx];
        g_ks[idx] = s;
    }
}

// ---------------------------------------------------------------------------
// attn_mma: per (ltile, bh): num = q[128x64] @ KVT^T (m16n8k16), z scalar,
// out = num * z -> g_n fp16. 256 threads = 8 warps (4 l x 2 e), warp 32x32.
// ---------------------------------------------------------------------------
__global__ __launch_bounds__(256)
void attn_mma()
{
    const int lt = blockIdx.x;            // 0..31 (128-row tiles)
    const int bh = blockIdx.y;
    const int b  = bh / NH;
    const int h  = bh % NH;
    const int tid  = threadIdx.x;
    const int warp = tid >> 5;
    const int lane = tid & 31;
    const int wm = warp & 3;              // l offset 32*wm
    const int we = warp >> 2;             // e offset 32*we

    __shared__ __align__(16) char qs[128 * 128];    // q tile 128x64 fp16 swz
    __shared__ __align__(16) char kvs[64 * 128];    // KVT 64x64 fp16 swz
    __shared__ float kss[DH];
    __shared__ float zs[128];
    const uint32_t qss = smem_u32(qs);
    const uint32_t kvss = smem_u32(kvs);

    const int lbase = lt * 128;
    const size_t qg = ((size_t)b * SEQ + lbase) * FF + h * DH;

    // loads: q 1024 chunks (4/thread), kvt 512 chunks (2/thread)
    #pragma unroll
    for (int i = 0; i < 4; i++) {
        const int cid = tid + i * 256;
        const int r = cid >> 3, ch = cid & 7;
        const uint32_t sw = (uint32_t)r * 128 + (uint32_t)((ch ^ (r & 7)) << 4);
        cp16(qss + sw, g_q + qg + (size_t)r * FF + ch * 8);
    }
    #pragma unroll
    for (int i = 0; i < 2; i++) {
        const int cid = tid + i * 256;
        const int r = cid >> 3, ch = cid & 7;
        const uint32_t sw = (uint32_t)r * 128 + (uint32_t)((ch ^ (r & 7)) << 4);
        cp16(kvss + sw, g_kvT + (size_t)bh * DH * DH + (size_t)r * DH + ch * 8);
    }
    if (tid < DH) kss[tid] = g_ks[(size_t)bh * DH + tid];
    CP_COMMIT();
    cp_wait<0>();
    __syncthreads();

    // z = 1 / (q . ksum) for 128 rows (threads 0-127)
    if (tid < 128) {
        const int r = tid;
        float s = 0.0f;
        #pragma unroll
        for (int ch = 0; ch < 8; ch++) {
            uint4 w = *(const uint4*)(qs + (size_t)r * 128 + ((ch ^ (r & 7)) << 4));
            const __half2* h2 = (const __half2*)&w;
            #pragma unroll
            for (int j = 0; j < 4; j++) {
                float2 f = __half22float2(h2[j]);
                s += f.x * kss[ch * 8 + 2 * j] + f.y * kss[ch * 8 + 2 * j + 1];
            }
        }
        zs[r] = 1.0f / s;
    }

    // MMA: warp tile 32 l x 32 e, K = 64 d (4 chunks of 16)
    float acc[2][4][4];
    #pragma unroll
    for (int i = 0; i < 2; i++)
        #pragma unroll
        for (int j = 0; j < 4; j++)
            #pragma unroll
            for (int q = 0; q < 4; q++) acc[i][j][q] = 0.0f;

    const int a_row0 = 32 * wm + (lane & 15);
    const int b_row0 = 32 * we + (lane & 15);
    const int lhi = lane >> 4;

    #pragma unroll
    for (int kc = 0; kc < 4; kc++) {
        const int ch = 2 * kc + lhi;
        uint32_t Af[2][4], Bf[4][2];
        #pragma unroll
        for (int mf = 0; mf < 2; mf++) {
            const int row = a_row0 + 16 * mf;
            ldsm_x4(Af[mf], qss + (uint32_t)row * 128
                          + (uint32_t)((ch ^ (row & 7)) << 4));
        }
        #pragma unroll
        for (int bq = 0; bq < 2; bq++) {
            const int row = b_row0 + 16 * bq;
            uint32_t t[4];
            ldsm_x4(t, kvss + (uint32_t)row * 128
                     + (uint32_t)((ch ^ (row & 7)) << 4));
            Bf[bq * 2][0] = t[0];     Bf[bq * 2][1] = t[2];
            Bf[bq * 2 + 1][0] = t[1]; Bf[bq * 2 + 1][1] = t[3];
        }
        #pragma unroll
        for (int mf = 0; mf < 2; mf++)
            #pragma unroll
            for (int nf = 0; nf < 4; nf++)
                mma16816(acc[mf][nf], Af[mf], Bf[nf]);
    }
    __syncthreads();   // zs ready (also keeps smem alive)

    // epilogue: out = acc * z, fp16 stores
    const int g = lane >> 2, tq = lane & 3;
    #pragma unroll
    for (int mf = 0; mf < 2; mf++) {
        const int rl0 = 32 * wm + 16 * mf + g;
        const float z0 = zs[rl0], z1 = zs[rl0 + 8];
        const size_t o0 = ((size_t)b * SEQ + lbase + rl0) * FF + h * DH;
        #pragma unroll
        for (int nf = 0; nf < 4; nf++) {
            const int col = 32 * we + 8 * nf + 2 * tq;
            *(__half2*)(g_n + o0 + col) =
                __floats2half2_rn(acc[mf][nf][0] * z0, acc[mf][nf][1] * z0);
            *(__half2*)(g_n + o0 + 8 * (size_t)FF + col) =
                __floats2half2_rn(acc[mf][nf][2] * z1, acc[mf][nf][3] * z1);
        }
    }
}

// ---------------------------------------------------------------------------
// launch
// ---------------------------------------------------------------------------
extern "C" void kernel_launch(void* const* d_in, const int* in_sizes, int n_in,
                              void* d_out, int out_size)
{
    const float* x  = (const float*)d_in[0];
    const float* Wq = (const float*)d_in[1];
    const float* bq = (const float*)d_in[2];
    const float* Wk = (const float*)d_in[3];
    const float* bk = (const float*)d_in[4];
    const float* Wv = (const float*)d_in[5];
    const float* bv = (const float*)d_in[6];
    const float* Wo = (const float*)d_in[7];
    const float* bo = (const float*)d_in[8];
    float* out = (float*)d_out;

    __half *px, *pn, *pw, *pq, *pk, *pv;
    cudaGetSymbolAddress((void**)&px, g_x);
    cudaGetSymbolAddress((void**)&pn, g_n);
    cudaGetSymbolAddress((void**)&pw, g_w);
    cudaGetSymbolAddress((void**)&pq, g_q);
    cudaGetSymbolAddress((void**)&pk, g_k);
    cudaGetSymbolAddress((void**)&pv, g_v);

    cudaFuncSetAttribute((const void*)mma_gemm<true,  __half>,
                         cudaFuncAttributeMaxDynamicSharedMemorySize, SMEM_DYN);
    cudaFuncSetAttribute((const void*)mma_gemm<false, __half>,
                         cudaFuncAttributeMaxDynamicSharedMemorySize, SMEM_DYN);
    cudaFuncSetAttribute((const void*)mma_gemm<false, float>,
                         cudaFuncAttributeMaxDynamicSharedMemorySize, SMEM_DYN);

    // weight transpose -> fp16
    conv_w4<<<dim3(FF / 32, FF / 32, 4), dim3(32, 8)>>>(Wq, Wk, Wv, Wo, pw);

    // x -> fp16
    conv_x<<<2048, 256>>>((const float4*)x, px, MROWS * FF / 4);

    dim3 ggrid(FF / GBN, MROWS / GBM);   // (6, 128)
    mma_gemm<true,  __half><<<ggrid, 256, SMEM_DYN>>>(px, pw + 0 * (size_t)FF * FF, bq, pq);
    mma_gemm<true,  __half><<<ggrid, 256, SMEM_DYN>>>(px, pw + 1 * (size_t)FF * FF, bk, pk);
    mma_gemm<false, __half><<<ggrid, 256, SMEM_DYN>>>(px, pw + 2 * (size_t)FF * FF, bv, pv);

    // kv summary (tensor cores) + reduce
    kv_partial_mma<<<dim3(BH, NSPLIT), 128>>>();
    kv_reduce_kernel<<<(BH * DH * DH + 255) / 256, 256>>>();

    // attention output (tensor cores)
    attn_mma<<<dim3(SEQ / 128, BH), 256>>>();

    // output projection
    mma_gemm<false, float><<<ggrid, 256, SMEM_DYN>>>(pn, pw + 3 * (size_t)FF * FF, bo, out);
}

// round 9
// speedup vs baseline: 7.2477x; 1.1189x over previous
#include <cuda_runtime.h>
#include <cuda_fp16.h>
#include <math.h>
#include <cstdint>

// ---------------------------------------------------------------------------
// Problem dims (fixed by the dataset)
// ---------------------------------------------------------------------------
#define BATCH 4
#define SEQ   4096
#define FF    768
#define NH    12
#define DH    64
#define MROWS (BATCH*SEQ)     // 16384
#define BH    (BATCH*NH)      // 48
#define NSPLIT 16
#define NPS (SEQ / NSPLIT)    // 256 sequence rows per split

// ---------------------------------------------------------------------------
// Static device scratch (no runtime allocation allowed)
// ---------------------------------------------------------------------------
__device__ __half  g_x [MROWS * FF];
__device__ __half  g_q [MROWS * FF];
__device__ __half  g_k [MROWS * FF];
__device__ __half  g_v [MROWS * FF];
__device__ __half  g_n [MROWS * FF];
__device__ __half  g_w [4][FF * FF];              // transposed weights fp16 [n][k]
__device__ float  g_kvp[NSPLIT * BH * DH * DH];
__device__ float  g_ksp[NSPLIT * BH * DH];
__device__ __half g_kvT[BH * DH * DH];
__device__ float  g_ks [BH * DH];

// ---------------------------------------------------------------------------
// PTX helpers
// ---------------------------------------------------------------------------
__device__ __forceinline__ uint32_t smem_u32(const void* p) {
    uint32_t a;
    asm("{ .reg .u64 t; cvta.to.shared.u64 t, %1; cvt.u32.u64 %0, t; }"
        : "=r"(a) : "l"(p));
    return a;
}

__device__ __forceinline__ void cp16(uint32_t dst, const void* src) {
    asm volatile("cp.async.cg.shared.global [%0], [%1], 16;" :: "r"(dst), "l"(src));
}
#define CP_COMMIT() asm volatile("cp.async.commit_group;" ::: "memory")
template <int N>
__device__ __forceinline__ void cp_wait() {
    asm volatile("cp.async.wait_group %0;" :: "n"(N) : "memory");
}

__device__ __forceinline__ void ldsm_x4(uint32_t* r, uint32_t addr) {
    asm volatile("ldmatrix.sync.aligned.m8n8.x4.shared.b16 {%0,%1,%2,%3}, [%4];"
                 : "=r"(r[0]), "=r"(r[1]), "=r"(r[2]), "=r"(r[3]) : "r"(addr));
}
__device__ __forceinline__ void ldsm_x4_t(uint32_t* r, uint32_t addr) {
    asm volatile("ldmatrix.sync.aligned.m8n8.x4.trans.shared.b16 {%0,%1,%2,%3}, [%4];"
                 : "=r"(r[0]), "=r"(r[1]), "=r"(r[2]), "=r"(r[3]) : "r"(addr));
}

__device__ __forceinline__ void mma16816(float* d, const uint32_t* a, const uint32_t* b) {
    asm volatile(
        "mma.sync.aligned.m16n8k16.row.col.f32.f16.f16.f32 "
        "{%0,%1,%2,%3}, {%4,%5,%6,%7}, {%8,%9}, {%0,%1,%2,%3};"
        : "+f"(d[0]), "+f"(d[1]), "+f"(d[2]), "+f"(d[3])
        : "r"(a[0]), "r"(a[1]), "r"(a[2]), "r"(a[3]), "r"(b[0]), "r"(b[1]));
}

__device__ __forceinline__ void store2(float* C, size_t idx, float a, float b) {
    *(float2*)(C + idx) = make_float2(a, b);
}
__device__ __forceinline__ void store2(__half* C, size_t idx, float a, float b) {
    *(__half2*)(C + idx) = __floats2half2_rn(a, b);
}

// ---------------------------------------------------------------------------
// gemm core: C[*,768] tile = A[M,K] @ W[N,K]^T + bias, optional phi (runtime)
// CTA 128x128, BK=64, 256 threads = 8 warps (2Mx4N), warp 64x32.
// 3-stage cp.async ring (96KB), prefetch distance 2, ONE barrier/iter.
// ---------------------------------------------------------------------------
#define GBM 128
#define GBN 128
#define GBK 64
#define A_BYTES  (128 * 128)
#define B_OFF  A_BYTES
#define STAGE_BYTES (2 * A_BYTES)      // 32 KB
#define SMEM_DYN (3 * STAGE_BYTES)     // 96 KB
#define NIT (FF / GBK)                 // 12

template <typename OutT>
__device__ __forceinline__ void gemm_core(
        const __half* __restrict__ A, const __half* __restrict__ B,
        const float* __restrict__ bias, OutT* __restrict__ C,
        bool phi, int brow, int bcol, char* dsm)
{
    const uint32_t sb = smem_u32(dsm);
    const int tid  = threadIdx.x;
    const int warp = tid >> 5;
    const int lane = tid & 31;
    const int wm   = warp & 1;
    const int wn   = warp >> 1;

    float acc[4][4][4];
    #pragma unroll
    for (int i = 0; i < 4; i++)
        #pragma unroll
        for (int j = 0; j < 4; j++)
            #pragma unroll
            for (int q = 0; q < 4; q++) acc[i][j][q] = 0.0f;

    // hoisted load addressing: 4 rows per thread (lr, lr+32, lr+64, lr+96)
    const int lr = tid >> 3, lc = tid & 7;
    uint32_t swo[4];
    const __half* gA[4];
    const __half* gB[4];
    #pragma unroll
    for (int i = 0; i < 4; i++) {
        const int row = lr + 32 * i;
        swo[i] = (uint32_t)row * 128 + (uint32_t)((lc ^ (row & 7)) << 4);
        gA[i] = A + (size_t)(brow + row) * FF + lc * 8;
        gB[i] = B + (size_t)(bcol + row) * FF + lc * 8;
    }

    const uint32_t stb0 = sb, stb1 = sb + STAGE_BYTES, stb2 = sb + 2 * STAGE_BYTES;

    // prologue: stages 0,1
    #pragma unroll
    for (int s = 0; s < 2; s++) {
        const uint32_t st = s ? stb1 : stb0;
        #pragma unroll
        for (int i = 0; i < 4; i++) {
            cp16(st + swo[i], gA[i]);
            cp16(st + B_OFF + swo[i], gB[i]);
            gA[i] += GBK;
            gB[i] += GBK;
        }
        CP_COMMIT();
    }

    // fragment addressing (XOR-folded swizzle)
    const int a_row0 = wm * 64 + (lane & 15);
    const int b_row0 = wn * 32 + (lane & 15);
    uint32_t a_base[4], b_base[2];
    #pragma unroll
    for (int mf = 0; mf < 4; mf++) {
        const int row = a_row0 + mf * 16;
        a_base[mf] = (uint32_t)row * 128 + (uint32_t)((row & 7) << 4);
    }
    #pragma unroll
    for (int bq = 0; bq < 2; bq++) {
        const int row = b_row0 + bq * 16;
        b_base[bq] = B_OFF + (uint32_t)row * 128 + (uint32_t)((row & 7) << 4);
    }
    const uint32_t khx = (uint32_t)(lane >> 4) << 4;

    int cur = 0, nxt = 2;
    for (int it = 0; it < NIT; it++) {
        if (it + 1 < NIT) cp_wait<1>(); else cp_wait<0>();
        __syncthreads();   // stage `it` visible to all; compute it-1 done everywhere

        if (it + 2 < NIT) {
            const uint32_t st2 = nxt == 0 ? stb0 : (nxt == 1 ? stb1 : stb2);
            #pragma unroll
            for (int i = 0; i < 4; i++) {
                cp16(st2 + swo[i], gA[i]);
                cp16(st2 + B_OFF + swo[i], gB[i]);
                gA[i] += GBK;
                gB[i] += GBK;
            }
            CP_COMMIT();
        }

        const uint32_t st = cur == 0 ? stb0 : (cur == 1 ? stb1 : stb2);
        #pragma unroll
        for (int ks = 0; ks < 4; ks++) {
            const uint32_t cx = ((uint32_t)(ks * 2) << 4) ^ khx;
            uint32_t Af[4][4], Bf[4][2];
            #pragma unroll
            for (int mf = 0; mf < 4; mf++)
                ldsm_x4(Af[mf], st + (a_base[mf] ^ cx));
            #pragma unroll
            for (int bq = 0; bq < 2; bq++) {
                uint32_t t[4];
                ldsm_x4(t, st + (b_base[bq] ^ cx));
                Bf[bq * 2][0] = t[0];     Bf[bq * 2][1] = t[2];
                Bf[bq * 2 + 1][0] = t[1]; Bf[bq * 2 + 1][1] = t[3];
            }
            #pragma unroll
            for (int mf = 0; mf < 4; mf++)
                #pragma unroll
                for (int nf = 0; nf < 4; nf++)
                    mma16816(acc[mf][nf], Af[mf], Bf[nf]);
        }
        cur = cur == 2 ? 0 : cur + 1;
        nxt = nxt == 2 ? 0 : nxt + 1;
    }

    // epilogue: bias + optional phi (runtime, uniform per block)
    #pragma unroll
    for (int nf = 0; nf < 4; nf++) {
        const int col = bcol + wn * 32 + nf * 8 + 2 * (lane & 3);
        const float b0 = bias[col], b1 = bias[col + 1];
        #pragma unroll
        for (int mf = 0; mf < 4; mf++) {
            const int r0 = brow + wm * 64 + mf * 16 + (lane >> 2);
            float e0 = acc[mf][nf][0] + b0, e1 = acc[mf][nf][1] + b1;
            float e2 = acc[mf][nf][2] + b0, e3 = acc[mf][nf][3] + b1;
            if (phi) {
                e0 = e0 > 0.0f ? e0 + 1.0f : expf(e0);
                e1 = e1 > 0.0f ? e1 + 1.0f : expf(e1);
                e2 = e2 > 0.0f ? e2 + 1.0f : expf(e2);
                e3 = e3 > 0.0f ? e3 + 1.0f : expf(e3);
            }
            store2(C, (size_t)r0 * FF + col, e0, e1);
            store2(C, (size_t)(r0 + 8) * FF + col, e2, e3);
        }
    }
}

// fused q/k/v projection: grid (6, 128, 3)
__global__ __launch_bounds__(256, 2)
void mma_qkv(const __half* __restrict__ A, const __half* __restrict__ W,
             const float* __restrict__ b0, const float* __restrict__ b1,
             const float* __restrict__ b2,
             __half* __restrict__ o0, __half* __restrict__ o1, __half* __restrict__ o2)
{
    extern __shared__ char dsm[];
    const int z = blockIdx.z;
    const float* bias = z == 0 ? b0 : (z == 1 ? b1 : b2);
    __half* C = z == 0 ? o0 : (z == 1 ? o1 : o2);
    gemm_core<__half>(A, W + (size_t)z * FF * FF, bias, C, z < 2,
                      blockIdx.y * GBM, blockIdx.x * GBN, dsm);
}

// output projection: grid (6, 128)
__global__ __launch_bounds__(256, 2)
void mma_o(const __half* __restrict__ A, const __half* __restrict__ W,
           const float* __restrict__ bias, float* __restrict__ C)
{
    extern __shared__ char dsm[];
    gemm_core<float>(A, W, bias, C, false, blockIdx.y * GBM, blockIdx.x * GBN, dsm);
}

// ---------------------------------------------------------------------------
// conversions
// ---------------------------------------------------------------------------
__global__ __launch_bounds__(256)
void conv_x(const float4* __restrict__ in, __half* __restrict__ x16, int n4)
{
    for (int i = blockIdx.x * 256 + threadIdx.x; i < n4; i += gridDim.x * 256) {
        float4 v = in[i];
        union { __half h[4]; uint2 u; } H;
        H.h[0] = __float2half_rn(v.x);
        H.h[1] = __float2half_rn(v.y);
        H.h[2] = __float2half_rn(v.z);
        H.h[3] = __float2half_rn(v.w);
        *(uint2*)(x16 + 4 * (size_t)i) = H.u;
    }
}

__global__ __launch_bounds__(256)
void conv_w4(const float* __restrict__ W0, const float* __restrict__ W1,
             const float* __restrict__ W2, const float* __restrict__ W3,
             __half* __restrict__ T)
{
    const float* Ws[4] = {W0, W1, W2, W3};
    const float* W = Ws[blockIdx.z];
    __half* th = T + (size_t)blockIdx.z * FF * FF;

    __shared__ float t[32][33];
    const int bx = blockIdx.x * 32, by = blockIdx.y * 32;
    const int tx = threadIdx.x, ty = threadIdx.y;
    #pragma unroll
    for (int i = ty; i < 32; i += 8)
        t[i][tx] = W[(size_t)(by + i) * FF + bx + tx];
    __syncthreads();
    #pragma unroll
    for (int i = ty; i < 32; i += 8)
        th[(size_t)(bx + i) * FF + by + tx] = __float2half_rn(t[tx][i]);
}

// ---------------------------------------------------------------------------
// kv_partial_mma: per (bh, split) KV^T[e][d] = sum_n v[n][e] k[n][d]
// ---------------------------------------------------------------------------
__global__ __launch_bounds__(128)
void kv_partial_mma()
{
    const int bh = blockIdx.x;
    const int sp = blockIdx.y;
    const int b  = bh / NH;
    const int h  = bh % NH;
    const int tid  = threadIdx.x;
    const int warp = tid >> 5;
    const int lane = tid & 31;

    __shared__ __align__(16) char kt[32 * 128];
    __shared__ __align__(16) char vt[32 * 128];
    const uint32_t kts = smem_u32(kt);
    const uint32_t vts = smem_u32(vt);

    float acc[8][4];
    #pragma unroll
    for (int i = 0; i < 8; i++)
        #pragma unroll
        for (int q = 0; q < 4; q++) acc[i][q] = 0.0f;
    float ksa[8][4];
    #pragma unroll
    for (int i = 0; i < 8; i++)
        #pragma unroll
        for (int q = 0; q < 4; q++) ksa[i][q] = 0.0f;

    const size_t gbase = ((size_t)b * SEQ + (size_t)sp * NPS) * FF + h * DH;
    const int lrow = lane & 15;
    const int lhi  = lane >> 4;

    uint32_t ones[4];
    #pragma unroll
    for (int i = 0; i < 4; i++) ones[i] = 0x3C003C00u;

    for (int c = 0; c < NPS / 32; c++) {
        #pragma unroll
        for (int i = 0; i < 2; i++) {
            const int cid = tid + i * 128;
            const int r = cid >> 3, ch = cid & 7;
            const uint32_t sw = (uint32_t)r * 128 + (uint32_t)((ch ^ (r & 7)) << 4);
            const size_t go = gbase + (size_t)(c * 32 + r) * FF + ch * 8;
            cp16(kts + sw, g_k + go);
            cp16(vts + sw, g_v + go);
        }
        CP_COMMIT();
        cp_wait<0>();
        __syncthreads();

        #pragma unroll
        for (int ks2 = 0; ks2 < 2; ks2++) {
            const int nb = ks2 * 16;
            uint32_t t[4], Afr[4];
            {
                const int row = nb + lrow;
                const int ch  = 2 * warp + lhi;
                ldsm_x4_t(t, vts + (uint32_t)row * 128
                             + (uint32_t)((ch ^ (row & 7)) << 4));
                Afr[0] = t[0]; Afr[1] = t[2]; Afr[2] = t[1]; Afr[3] = t[3];
            }
            uint32_t Bf[8][2];
            #pragma unroll
            for (int j = 0; j < 4; j++) {
                const int row = nb + lrow;
                const int ch  = 2 * j + lhi;
                uint32_t u[4];
                ldsm_x4_t(u, kts + (uint32_t)row * 128
                             + (uint32_t)((ch ^ (row & 7)) << 4));
                Bf[2 * j][0] = u[0];     Bf[2 * j][1] = u[1];
                Bf[2 * j + 1][0] = u[2]; Bf[2 * j + 1][1] = u[3];
            }
            #pragma unroll
            for (int dg = 0; dg < 8; dg++)
                mma16816(acc[dg], Afr, Bf[dg]);
            if (warp == 0) {
                #pragma unroll
                for (int dg = 0; dg < 8; dg++)
                    mma16816(ksa[dg], ones, Bf[dg]);
            }
        }
        __syncthreads();
    }

    const int g = lane >> 2, tq = lane & 3;
    float* kvout = g_kvp + ((size_t)sp * BH + bh) * DH * DH;
    #pragma unroll
    for (int dg = 0; dg < 8; dg++) {
        const int e0 = 16 * warp + g;
        const int d0 = 8 * dg + 2 * tq;
        store2(kvout, (size_t)e0 * DH + d0,       acc[dg][0], acc[dg][1]);
        store2(kvout, (size_t)(e0 + 8) * DH + d0, acc[dg][2], acc[dg][3]);
    }
    if (warp == 0 && g == 0) {
        float* ksout = g_ksp + ((size_t)sp * BH + bh) * DH;
        #pragma unroll
        for (int dg = 0; dg < 8; dg++) {
            ksout[8 * dg + 2 * tq]     = ksa[dg][0];
            ksout[8 * dg + 2 * tq + 1] = ksa[dg][1];
        }
    }
}

__global__ __launch_bounds__(256)
void kv_reduce_kernel()
{
    const int idx = blockIdx.x * 256 + threadIdx.x;
    if (idx < BH * DH * DH) {
        float s = 0.0f;
        #pragma unroll
        for (int p = 0; p < NSPLIT; p++) s += g_kvp[(size_t)p * (BH * DH * DH) + idx];
        g_kvT[idx] = __float2half_rn(s);
    }
    if (idx < BH * DH) {
        float s = 0.0f;
        #pragma unroll
        for (int p = 0; p < NSPLIT; p++) s += g_ksp[(size_t)p * (BH * DH) + idx];
        g_ks[idx] = s;
    }
}

// ---------------------------------------------------------------------------
// attn_mma: num = q[128x64] @ KVT^T; out = num * 1/(q.ksum) -> fp16
// ---------------------------------------------------------------------------
__global__ __launch_bounds__(256)
void attn_mma()
{
    const int lt = blockIdx.x;
    const int bh = blockIdx.y;
    const int b  = bh / NH;
    const int h  = bh % NH;
    const int tid  = threadIdx.x;
    const int warp = tid >> 5;
    const int lane = tid & 31;
    const int wm = warp & 3;
    const int we = warp >> 2;

    __shared__ __align__(16) char qs[128 * 128];
    __shared__ __align__(16) char kvs[64 * 128];
    __shared__ float kss[DH];
    __shared__ float zs[128];
    const uint32_t qss = smem_u32(qs);
    const uint32_t kvss = smem_u32(kvs);

    const int lbase = lt * 128;
    const size_t qg = ((size_t)b * SEQ + lbase) * FF + h * DH;

    #pragma unroll
    for (int i = 0; i < 4; i++) {
        const int cid = tid + i * 256;
        const int r = cid >> 3, ch = cid & 7;
        const uint32_t sw = (uint32_t)r * 128 + (uint32_t)((ch ^ (r & 7)) << 4);
        cp16(qss + sw, g_q + qg + (size_t)r * FF + ch * 8);
    }
    #pragma unroll
    for (int i = 0; i < 2; i++) {
        const int cid = tid + i * 256;
        const int r = cid >> 3, ch = cid & 7;
        const uint32_t sw = (uint32_t)r * 128 + (uint32_t)((ch ^ (r & 7)) << 4);
        cp16(kvss + sw, g_kvT + (size_t)bh * DH * DH + (size_t)r * DH + ch * 8);
    }
    if (tid < DH) kss[tid] = g_ks[(size_t)bh * DH + tid];
    CP_COMMIT();
    cp_wait<0>();
    __syncthreads();

    if (tid < 128) {
        const int r = tid;
        float s = 0.0f;
        #pragma unroll
        for (int ch = 0; ch < 8; ch++) {
            uint4 w = *(const uint4*)(qs + (size_t)r * 128 + ((ch ^ (r & 7)) << 4));
            const __half2* h2 = (const __half2*)&w;
            #pragma unroll
            for (int j = 0; j < 4; j++) {
                float2 f = __half22float2(h2[j]);
                s += f.x * kss[ch * 8 + 2 * j] + f.y * kss[ch * 8 + 2 * j + 1];
            }
        }
        zs[r] = 1.0f / s;
    }

    float acc[2][4][4];
    #pragma unroll
    for (int i = 0; i < 2; i++)
        #pragma unroll
        for (int j = 0; j < 4; j++)
            #pragma unroll
            for (int q = 0; q < 4; q++) acc[i][j][q] = 0.0f;

    const int a_row0 = 32 * wm + (lane & 15);
    const int b_row0 = 32 * we + (lane & 15);
    const int lhi = lane >> 4;

    #pragma unroll
    for (int kc = 0; kc < 4; kc++) {
        const int ch = 2 * kc + lhi;
        uint32_t Af[2][4], Bf[4][2];
        #pragma unroll
        for (int mf = 0; mf < 2; mf++) {
            const int row = a_row0 + 16 * mf;
            ldsm_x4(Af[mf], qss + (uint32_t)row * 128
                          + (uint32_t)((ch ^ (row & 7)) << 4));
        }
        #pragma unroll
        for (int bq = 0; bq < 2; bq++) {
            const int row = b_row0 + 16 * bq;
            uint32_t t[4];
            ldsm_x4(t, kvss + (uint32_t)row * 128
                     + (uint32_t)((ch ^ (row & 7)) << 4));
            Bf[bq * 2][0] = t[0];     Bf[bq * 2][1] = t[2];
            Bf[bq * 2 + 1][0] = t[1]; Bf[bq * 2 + 1][1] = t[3];
        }
        #pragma unroll
        for (int mf = 0; mf < 2; mf++)
            #pragma unroll
            for (int nf = 0; nf < 4; nf++)
                mma16816(acc[mf][nf], Af[mf], Bf[nf]);
    }
    __syncthreads();

    const int g = lane >> 2, tq = lane & 3;
    #pragma unroll
    for (int mf = 0; mf < 2; mf++) {
        const int rl0 = 32 * wm + 16 * mf + g;
        const float z0 = zs[rl0], z1 = zs[rl0 + 8];
        const size_t o0 = ((size_t)b * SEQ + lbase + rl0) * FF + h * DH;
        #pragma unroll
        for (int nf = 0; nf < 4; nf++) {
            const int col = 32 * we + 8 * nf + 2 * tq;
            *(__half2*)(g_n + o0 + col) =
                __floats2half2_rn(acc[mf][nf][0] * z0, acc[mf][nf][1] * z0);
            *(__half2*)(g_n + o0 + 8 * (size_t)FF + col) =
                __floats2half2_rn(acc[mf][nf][2] * z1, acc[mf][nf][3] * z1);
        }
    }
}

// ---------------------------------------------------------------------------
// launch
// ---------------------------------------------------------------------------
extern "C" void kernel_launch(void* const* d_in, const int* in_sizes, int n_in,
                              void* d_out, int out_size)
{
    const float* x  = (const float*)d_in[0];
    const float* Wq = (const float*)d_in[1];
    const float* bq = (const float*)d_in[2];
    const float* Wk = (const float*)d_in[3];
    const float* bk = (const float*)d_in[4];
    const float* Wv = (const float*)d_in[5];
    const float* bv = (const float*)d_in[6];
    const float* Wo = (const float*)d_in[7];
    const float* bo = (const float*)d_in[8];
    float* out = (float*)d_out;

    __half *px, *pn, *pw, *pq, *pk, *pv;
    cudaGetSymbolAddress((void**)&px, g_x);
    cudaGetSymbolAddress((void**)&pn, g_n);
    cudaGetSymbolAddress((void**)&pw, g_w);
    cudaGetSymbolAddress((void**)&pq, g_q);
    cudaGetSymbolAddress((void**)&pk, g_k);
    cudaGetSymbolAddress((void**)&pv, g_v);

    cudaFuncSetAttribute((const void*)mma_qkv,
                         cudaFuncAttributeMaxDynamicSharedMemorySize, SMEM_DYN);
    cudaFuncSetAttribute((const void*)mma_o,
                         cudaFuncAttributeMaxDynamicSharedMemorySize, SMEM_DYN);

    // weight transpose -> fp16
    conv_w4<<<dim3(FF / 32, FF / 32, 4), dim3(32, 8)>>>(Wq, Wk, Wv, Wo, pw);

    // x -> fp16
    conv_x<<<2048, 256>>>((const float4*)x, px, MROWS * FF / 4);

    // fused q/k/v projections
    mma_qkv<<<dim3(FF / GBN, MROWS / GBM, 3), 256, SMEM_DYN>>>(
        px, pw, bq, bk, bv, pq, pk, pv);

    // kv summary + reduce
    kv_partial_mma<<<dim3(BH, NSPLIT), 128>>>();
    kv_reduce_kernel<<<(BH * DH * DH + 255) / 256, 256>>>();

    // attention output
    attn_mma<<<dim3(SEQ / 128, BH), 256>>>();

    // output projection
    mma_o<<<dim3(FF / GBN, MROWS / GBM), 256, SMEM_DYN>>>(
        pn, pw + 3 * (size_t)FF * FF, bo, out);
}